// round 1
// baseline (speedup 1.0000x reference)
#include <cuda_runtime.h>

#define SEQ 2048
#define DM  1024
#define DI  64
#define NB  8

// Scratch for projected Q (pre-scaled by 1/8), K, V: [B*SEQ][64] each.
__device__ float g_q[NB*SEQ*DI];
__device__ float g_k[NB*SEQ*DI];
__device__ float g_v[NB*SEQ*DI];

// ---------------------------------------------------------------------------
// QKV projection: C[16384 x 64] = X[16384 x 1024] * W[1024 x 64] + b
// Tile 128 rows x 64 cols, 256 threads, 8x4 micro-tile, K-chunks of 32.
// blockIdx.y selects (Wq->g_q scaled, Wk->g_k, Wv->g_v).
// ---------------------------------------------------------------------------
#define PK   32
#define ASTR 132   // padded row stride for transposed A tile (mult of 4 for float4)

__global__ __launch_bounds__(256, 2)
void proj_kernel(const float* __restrict__ X,
                 const float* __restrict__ Wq, const float* __restrict__ bq,
                 const float* __restrict__ Wk, const float* __restrict__ bk,
                 const float* __restrict__ Wv, const float* __restrict__ bv)
{
    __shared__ float As[PK][ASTR];   // transposed: As[k][row]
    __shared__ float Bs[PK][64];     // Bs[k][col]

    const float* W; const float* bi; float* dst; float scale = 1.0f;
    if (blockIdx.y == 0)      { W = Wq; bi = bq; dst = g_q; scale = 0.125f; }
    else if (blockIdx.y == 1) { W = Wk; bi = bk; dst = g_k; }
    else                      { W = Wv; bi = bv; dst = g_v; }

    const int t  = threadIdx.x;
    const int tx = t & 15;        // col group (4 cols)
    const int ty = t >> 4;        // row group (8 rows)
    const size_t r0 = (size_t)blockIdx.x * 128;

    float acc[8][4];
    #pragma unroll
    for (int i = 0; i < 8; i++)
        #pragma unroll
        for (int j = 0; j < 4; j++) acc[i][j] = 0.f;

    for (int kb = 0; kb < DM; kb += PK) {
        // Load A tile 128x32, store transposed
        #pragma unroll
        for (int it = 0; it < 4; it++) {
            int idx = t + it * 256;
            int row = idx >> 3;
            int kc  = (idx & 7) << 2;
            float4 a = *(const float4*)&X[(r0 + row) * DM + kb + kc];
            As[kc+0][row] = a.x; As[kc+1][row] = a.y;
            As[kc+2][row] = a.z; As[kc+3][row] = a.w;
        }
        // Load B tile 32x64
        #pragma unroll
        for (int it = 0; it < 2; it++) {
            int idx = t + it * 256;
            int k = idx >> 4;
            int c = (idx & 15) << 2;
            *(float4*)&Bs[k][c] = *(const float4*)&W[(size_t)(kb + k) * DI + c];
        }
        __syncthreads();

        #pragma unroll
        for (int k = 0; k < PK; k++) {
            float4 a0 = *(const float4*)&As[k][ty*8];
            float4 a1 = *(const float4*)&As[k][ty*8 + 4];
            float4 b4 = *(const float4*)&Bs[k][tx*4];
            float av[8] = {a0.x,a0.y,a0.z,a0.w,a1.x,a1.y,a1.z,a1.w};
            float bv4[4] = {b4.x,b4.y,b4.z,b4.w};
            #pragma unroll
            for (int i = 0; i < 8; i++)
                #pragma unroll
                for (int j = 0; j < 4; j++)
                    acc[i][j] = fmaf(av[i], bv4[j], acc[i][j]);
        }
        __syncthreads();
    }

    float4 bb = *(const float4*)&bi[tx*4];
    float bv4[4] = {bb.x, bb.y, bb.z, bb.w};
    #pragma unroll
    for (int i = 0; i < 8; i++) {
        float4 o;
        o.x = (acc[i][0] + bv4[0]) * scale;
        o.y = (acc[i][1] + bv4[1]) * scale;
        o.z = (acc[i][2] + bv4[2]) * scale;
        o.w = (acc[i][3] + bv4[3]) * scale;
        *(float4*)&dst[(r0 + ty*8 + i) * DI + tx*4] = o;
    }
}

// ---------------------------------------------------------------------------
// Flash attention + fused output projection.
// q-tile = 64 rows, 128 threads (8x4 micro-tile: ty in [0,8) owns 8 rows,
// tx in [0,16) owns 4 cols). Online softmax; row stats replicated across the
// 16 tx lanes via shfl.xor within the half-warp. Epilogue: out = (O/l)*W0+b0.
// Grid: 256 blocks = 8 batches x 32 q-tiles, scheduled cost-descending.
// ---------------------------------------------------------------------------
#define TSTR 68    // padded stride for transposed 64x64 smem tiles

__global__ __launch_bounds__(128)
void attn_kernel(const float* __restrict__ W0, const float* __restrict__ b0,
                 float* __restrict__ out)
{
    extern __shared__ float sm[];
    float (*Qt)[TSTR]  = (float(*)[TSTR])(sm);                 // Q^T: [d][i]
    float (*KWs)[TSTR] = (float(*)[TSTR])(sm + 64*TSTR);       // K^T: [d][j]; later W0 [e][o]
    float (*Pt)[TSTR]  = (float(*)[TSTR])(sm + 2*64*TSTR);     // P^T: [j][i]; later O^T [e][i]
    float (*Vs)[64]    = (float(*)[64])  (sm + 3*64*TSTR);     // V: [j][e]

    const int t  = threadIdx.x;
    const int tx = t & 15;
    const int ty = t >> 4;
    const int b  = blockIdx.x & 7;
    const int qt = 31 - (blockIdx.x >> 3);   // high-cost q-tiles first
    const int q0 = qt * 64;

    // Load Q tile transposed (already scaled by 1/8 at projection)
    const float* qp = g_q + ((size_t)b * SEQ + q0) * DI;
    #pragma unroll
    for (int it = 0; it < 8; it++) {
        int idx = t + it * 128;
        int row = idx >> 4;
        int dc  = (idx & 15) << 2;
        float4 a = *(const float4*)&qp[row * DI + dc];
        Qt[dc+0][row] = a.x; Qt[dc+1][row] = a.y;
        Qt[dc+2][row] = a.z; Qt[dc+3][row] = a.w;
    }

    float m[8], l[8], acc[8][4];
    #pragma unroll
    for (int i = 0; i < 8; i++) {
        m[i] = -1e30f; l[i] = 0.f;
        #pragma unroll
        for (int e = 0; e < 4; e++) acc[i][e] = 0.f;
    }

    for (int jt = 0; jt <= qt; jt++) {
        const float* kp = g_k + ((size_t)b * SEQ + jt * 64) * DI;
        const float* vp = g_v + ((size_t)b * SEQ + jt * 64) * DI;
        __syncthreads();   // previous O-accum done reading Vs/Pt
        #pragma unroll
        for (int it = 0; it < 8; it++) {
            int idx = t + it * 128;
            int row = idx >> 4;
            int dc  = (idx & 15) << 2;
            float4 a = *(const float4*)&kp[row * DI + dc];
            KWs[dc+0][row] = a.x; KWs[dc+1][row] = a.y;
            KWs[dc+2][row] = a.z; KWs[dc+3][row] = a.w;
            *(float4*)&Vs[row][dc] = *(const float4*)&vp[row * DI + dc];
        }
        __syncthreads();

        // S = Q K^T  (8x4 per thread)
        float s[8][4];
        #pragma unroll
        for (int i = 0; i < 8; i++)
            #pragma unroll
            for (int j = 0; j < 4; j++) s[i][j] = 0.f;

        #pragma unroll 8
        for (int d = 0; d < 64; d++) {
            float4 a0 = *(const float4*)&Qt[d][ty*8];
            float4 a1 = *(const float4*)&Qt[d][ty*8 + 4];
            float4 k4 = *(const float4*)&KWs[d][tx*4];
            float av[8] = {a0.x,a0.y,a0.z,a0.w,a1.x,a1.y,a1.z,a1.w};
            float kv[4] = {k4.x,k4.y,k4.z,k4.w};
            #pragma unroll
            for (int i = 0; i < 8; i++)
                #pragma unroll
                for (int j = 0; j < 4; j++)
                    s[i][j] = fmaf(av[i], kv[j], s[i][j]);
        }

        if (jt == qt) {  // causal mask on the diagonal tile
            #pragma unroll
            for (int i = 0; i < 8; i++)
                #pragma unroll
                for (int j = 0; j < 4; j++)
                    if (tx*4 + j > ty*8 + i) s[i][j] = -1e30f;
        }

        // Online softmax per row (stats replicated across tx lanes)
        #pragma unroll
        for (int i = 0; i < 8; i++) {
            float mx = fmaxf(fmaxf(s[i][0], s[i][1]), fmaxf(s[i][2], s[i][3]));
            mx = fmaxf(mx, __shfl_xor_sync(0xffffffffu, mx, 1));
            mx = fmaxf(mx, __shfl_xor_sync(0xffffffffu, mx, 2));
            mx = fmaxf(mx, __shfl_xor_sync(0xffffffffu, mx, 4));
            mx = fmaxf(mx, __shfl_xor_sync(0xffffffffu, mx, 8));
            float nm = fmaxf(m[i], mx);
            float sc = __expf(m[i] - nm);
            float rs = 0.f;
            #pragma unroll
            for (int j = 0; j < 4; j++) {
                float p = __expf(s[i][j] - nm);
                s[i][j] = p; rs += p;
            }
            rs += __shfl_xor_sync(0xffffffffu, rs, 1);
            rs += __shfl_xor_sync(0xffffffffu, rs, 2);
            rs += __shfl_xor_sync(0xffffffffu, rs, 4);
            rs += __shfl_xor_sync(0xffffffffu, rs, 8);
            l[i] = l[i] * sc + rs;
            m[i] = nm;
            #pragma unroll
            for (int e = 0; e < 4; e++) acc[i][e] *= sc;
            #pragma unroll
            for (int j = 0; j < 4; j++) Pt[tx*4 + j][ty*8 + i] = s[i][j];
        }
        __syncthreads();

        // O += P V
        #pragma unroll 8
        for (int j = 0; j < 64; j++) {
            float4 p0 = *(const float4*)&Pt[j][ty*8];
            float4 p1 = *(const float4*)&Pt[j][ty*8 + 4];
            float4 v4 = *(const float4*)&Vs[j][tx*4];
            float pv[8] = {p0.x,p0.y,p0.z,p0.w,p1.x,p1.y,p1.z,p1.w};
            float vv[4] = {v4.x,v4.y,v4.z,v4.w};
            #pragma unroll
            for (int i = 0; i < 8; i++)
                #pragma unroll
                for (int e = 0; e < 4; e++)
                    acc[i][e] = fmaf(pv[i], vv[e], acc[i][e]);
        }
    }

    // Epilogue: normalize, then fused out = O * W0 + b0
    __syncthreads();
    #pragma unroll
    for (int i = 0; i < 8; i++) {
        float inv = 1.0f / l[i];
        #pragma unroll
        for (int e = 0; e < 4; e++) Pt[tx*4 + e][ty*8 + i] = acc[i][e] * inv;
    }
    #pragma unroll
    for (int it = 0; it < 8; it++) {
        int idx = t + it * 128;
        int row = idx >> 4;
        int c   = (idx & 15) << 2;
        *(float4*)&KWs[row][c] = *(const float4*)&W0[row * 64 + c];
    }
    __syncthreads();

    float res[8][4];
    #pragma unroll
    for (int i = 0; i < 8; i++)
        #pragma unroll
        for (int j = 0; j < 4; j++) res[i][j] = 0.f;

    #pragma unroll 8
    for (int e = 0; e < 64; e++) {
        float4 a0 = *(const float4*)&Pt[e][ty*8];
        float4 a1 = *(const float4*)&Pt[e][ty*8 + 4];
        float4 w4 = *(const float4*)&KWs[e][tx*4];
        float av[8] = {a0.x,a0.y,a0.z,a0.w,a1.x,a1.y,a1.z,a1.w};
        float wv[4] = {w4.x,w4.y,w4.z,w4.w};
        #pragma unroll
        for (int i = 0; i < 8; i++)
            #pragma unroll
            for (int o = 0; o < 4; o++)
                res[i][o] = fmaf(av[i], wv[o], res[i][o]);
    }

    float4 bb = *(const float4*)&b0[tx*4];
    float bv4[4] = {bb.x, bb.y, bb.z, bb.w};
    #pragma unroll
    for (int i = 0; i < 8; i++) {
        float4 o4;
        o4.x = res[i][0] + bv4[0];
        o4.y = res[i][1] + bv4[1];
        o4.z = res[i][2] + bv4[2];
        o4.w = res[i][3] + bv4[3];
        *(float4*)&out[((size_t)b * SEQ + q0 + ty*8 + i) * DI + tx*4] = o4;
    }
}

// ---------------------------------------------------------------------------
extern "C" void kernel_launch(void* const* d_in, const int* in_sizes, int n_in,
                              void* d_out, int out_size)
{
    const float* X  = (const float*)d_in[0];
    const float* Wk = (const float*)d_in[1];
    const float* bk = (const float*)d_in[2];
    const float* Wq = (const float*)d_in[3];
    const float* bq = (const float*)d_in[4];
    const float* Wv = (const float*)d_in[5];
    const float* bv = (const float*)d_in[6];
    const float* W0 = (const float*)d_in[7];
    const float* b0 = (const float*)d_in[8];
    float* out = (float*)d_out;

    const int attn_smem = (3 * 64 * TSTR + 64 * 64) * (int)sizeof(float);  // 68608 B
    cudaFuncSetAttribute(attn_kernel, cudaFuncAttributeMaxDynamicSharedMemorySize,
                         attn_smem);

    dim3 pg(NB * SEQ / 128, 3);
    proj_kernel<<<pg, 256>>>(X, Wq, bq, Wk, bk, Wv, bv);
    attn_kernel<<<NB * 32, 128, attn_smem>>>(W0, b0, out);
}

// round 4
// speedup vs baseline: 1.2001x; 1.2001x over previous
#include <cuda_runtime.h>

#define SEQ 2048
#define DM  1024
#define DI  64
#define NB  8

// Scratch for projected Q (pre-scaled by 1/8), K, V: [B*SEQ][64] each.
__device__ float g_q[NB*SEQ*DI];
__device__ float g_k[NB*SEQ*DI];
__device__ float g_v[NB*SEQ*DI];

// Split-KV partials: up to 4 splits per (b, qt). unit = ((b*32+qt)*4 + s)
__device__ float g_opart[NB*32*4*64*64];   // unnormalized O partials
__device__ float g_mpart[NB*32*4*64];      // row max per partial
__device__ float g_lpart[NB*32*4*64];      // row sum per partial

// ---------------------------------------------------------------------------
// QKV projection: C[16384 x 64] = X[16384 x 1024] * W[1024 x 64] + b
// ---------------------------------------------------------------------------
#define PK   32
#define ASTR 132

__global__ __launch_bounds__(256, 2)
void proj_kernel(const float* __restrict__ X,
                 const float* __restrict__ Wq, const float* __restrict__ bq,
                 const float* __restrict__ Wk, const float* __restrict__ bk,
                 const float* __restrict__ Wv, const float* __restrict__ bv)
{
    __shared__ float As[PK][ASTR];
    __shared__ float Bs[PK][64];

    const float* W; const float* bi; float* dst; float scale = 1.0f;
    if (blockIdx.y == 0)      { W = Wq; bi = bq; dst = g_q; scale = 0.125f; }
    else if (blockIdx.y == 1) { W = Wk; bi = bk; dst = g_k; }
    else                      { W = Wv; bi = bv; dst = g_v; }

    const int t  = threadIdx.x;
    const int tx = t & 15;
    const int ty = t >> 4;
    const size_t r0 = (size_t)blockIdx.x * 128;

    float acc[8][4];
    #pragma unroll
    for (int i = 0; i < 8; i++)
        #pragma unroll
        for (int j = 0; j < 4; j++) acc[i][j] = 0.f;

    for (int kb = 0; kb < DM; kb += PK) {
        #pragma unroll
        for (int it = 0; it < 4; it++) {
            int idx = t + it * 256;
            int row = idx >> 3;
            int kc  = (idx & 7) << 2;
            float4 a = *(const float4*)&X[(r0 + row) * DM + kb + kc];
            As[kc+0][row] = a.x; As[kc+1][row] = a.y;
            As[kc+2][row] = a.z; As[kc+3][row] = a.w;
        }
        #pragma unroll
        for (int it = 0; it < 2; it++) {
            int idx = t + it * 256;
            int k = idx >> 4;
            int c = (idx & 15) << 2;
            *(float4*)&Bs[k][c] = *(const float4*)&W[(size_t)(kb + k) * DI + c];
        }
        __syncthreads();

        #pragma unroll
        for (int k = 0; k < PK; k++) {
            float4 a0 = *(const float4*)&As[k][ty*8];
            float4 a1 = *(const float4*)&As[k][ty*8 + 4];
            float4 b4 = *(const float4*)&Bs[k][tx*4];
            float av[8] = {a0.x,a0.y,a0.z,a0.w,a1.x,a1.y,a1.z,a1.w};
            float bv4[4] = {b4.x,b4.y,b4.z,b4.w};
            #pragma unroll
            for (int i = 0; i < 8; i++)
                #pragma unroll
                for (int j = 0; j < 4; j++)
                    acc[i][j] = fmaf(av[i], bv4[j], acc[i][j]);
        }
        __syncthreads();
    }

    float4 bb = *(const float4*)&bi[tx*4];
    float bv4[4] = {bb.x, bb.y, bb.z, bb.w};
    #pragma unroll
    for (int i = 0; i < 8; i++) {
        float4 o;
        o.x = (acc[i][0] + bv4[0]) * scale;
        o.y = (acc[i][1] + bv4[1]) * scale;
        o.z = (acc[i][2] + bv4[2]) * scale;
        o.w = (acc[i][3] + bv4[3]) * scale;
        *(float4*)&dst[(r0 + ty*8 + i) * DI + tx*4] = o;
    }
}

// ---------------------------------------------------------------------------
// Split-KV flash attention, partial pass.
// Work unit = (b, qt, split). Split covers up to 8 kv-tiles. 640 blocks total.
// Emits unnormalized O partial + (m, l) per row to scratch.
// ---------------------------------------------------------------------------
#define TSTR 68
#define CHUNK 8

__global__ __launch_bounds__(128)
void attn_part_kernel()
{
    extern __shared__ float sm[];
    float (*Qt)[TSTR] = (float(*)[TSTR])(sm);               // Q^T: [d][i]
    float (*Kt)[TSTR] = (float(*)[TSTR])(sm + 64*TSTR);     // K^T: [d][j]
    float (*Pt)[TSTR] = (float(*)[TSTR])(sm + 2*64*TSTR);   // P^T: [j][i]
    float (*Vs)[64]   = (float(*)[64])  (sm + 3*64*TSTR);   // V: [j][e]

    const int t  = threadIdx.x;
    const int tx = t & 15;
    const int ty = t >> 4;

    // Decode work unit: 80 units per batch.
    const int b = blockIdx.x / 80;
    int u = blockIdx.x % 80;
    int qt = 0, s = 0;
    #pragma unroll 1
    for (qt = 0; qt < 32; qt++) {
        int ns = (qt >> 3) + 1;          // ceil((qt+1)/8)
        if (u < ns) { s = u; break; }
        u -= ns;
    }
    const int q0  = qt * 64;
    const int jt0 = s * CHUNK;
    const int jt1 = min(jt0 + CHUNK, qt + 1);

    // Load Q tile transposed (pre-scaled at projection)
    const float* qp = g_q + ((size_t)b * SEQ + q0) * DI;
    #pragma unroll
    for (int it = 0; it < 8; it++) {
        int idx = t + it * 128;
        int row = idx >> 4;
        int dc  = (idx & 15) << 2;
        float4 a = *(const float4*)&qp[row * DI + dc];
        Qt[dc+0][row] = a.x; Qt[dc+1][row] = a.y;
        Qt[dc+2][row] = a.z; Qt[dc+3][row] = a.w;
    }

    float m[8], l[8], acc[8][4];
    #pragma unroll
    for (int i = 0; i < 8; i++) {
        m[i] = -1e30f; l[i] = 0.f;
        #pragma unroll
        for (int e = 0; e < 4; e++) acc[i][e] = 0.f;
    }

    for (int jt = jt0; jt < jt1; jt++) {
        const float* kp = g_k + ((size_t)b * SEQ + jt * 64) * DI;
        const float* vp = g_v + ((size_t)b * SEQ + jt * 64) * DI;
        __syncthreads();
        #pragma unroll
        for (int it = 0; it < 8; it++) {
            int idx = t + it * 128;
            int row = idx >> 4;
            int dc  = (idx & 15) << 2;
            float4 a = *(const float4*)&kp[row * DI + dc];
            Kt[dc+0][row] = a.x; Kt[dc+1][row] = a.y;
            Kt[dc+2][row] = a.z; Kt[dc+3][row] = a.w;
            *(float4*)&Vs[row][dc] = *(const float4*)&vp[row * DI + dc];
        }
        __syncthreads();

        float sv[8][4];
        #pragma unroll
        for (int i = 0; i < 8; i++)
            #pragma unroll
            for (int j = 0; j < 4; j++) sv[i][j] = 0.f;

        #pragma unroll 8
        for (int d = 0; d < 64; d++) {
            float4 a0 = *(const float4*)&Qt[d][ty*8];
            float4 a1 = *(const float4*)&Qt[d][ty*8 + 4];
            float4 k4 = *(const float4*)&Kt[d][tx*4];
            float av[8] = {a0.x,a0.y,a0.z,a0.w,a1.x,a1.y,a1.z,a1.w};
            float kv[4] = {k4.x,k4.y,k4.z,k4.w};
            #pragma unroll
            for (int i = 0; i < 8; i++)
                #pragma unroll
                for (int j = 0; j < 4; j++)
                    sv[i][j] = fmaf(av[i], kv[j], sv[i][j]);
        }

        if (jt == qt) {
            #pragma unroll
            for (int i = 0; i < 8; i++)
                #pragma unroll
                for (int j = 0; j < 4; j++)
                    if (tx*4 + j > ty*8 + i) sv[i][j] = -1e30f;
        }

        #pragma unroll
        for (int i = 0; i < 8; i++) {
            float mx = fmaxf(fmaxf(sv[i][0], sv[i][1]), fmaxf(sv[i][2], sv[i][3]));
            mx = fmaxf(mx, __shfl_xor_sync(0xffffffffu, mx, 1));
            mx = fmaxf(mx, __shfl_xor_sync(0xffffffffu, mx, 2));
            mx = fmaxf(mx, __shfl_xor_sync(0xffffffffu, mx, 4));
            mx = fmaxf(mx, __shfl_xor_sync(0xffffffffu, mx, 8));
            float nm = fmaxf(m[i], mx);
            float sc = __expf(m[i] - nm);
            float rs = 0.f;
            #pragma unroll
            for (int j = 0; j < 4; j++) {
                float p = __expf(sv[i][j] - nm);
                sv[i][j] = p; rs += p;
            }
            rs += __shfl_xor_sync(0xffffffffu, rs, 1);
            rs += __shfl_xor_sync(0xffffffffu, rs, 2);
            rs += __shfl_xor_sync(0xffffffffu, rs, 4);
            rs += __shfl_xor_sync(0xffffffffu, rs, 8);
            l[i] = l[i] * sc + rs;
            m[i] = nm;
            #pragma unroll
            for (int e = 0; e < 4; e++) acc[i][e] *= sc;
            #pragma unroll
            for (int j = 0; j < 4; j++) Pt[tx*4 + j][ty*8 + i] = sv[i][j];
        }
        __syncthreads();

        #pragma unroll 8
        for (int j = 0; j < 64; j++) {
            float4 p0 = *(const float4*)&Pt[j][ty*8];
            float4 p1 = *(const float4*)&Pt[j][ty*8 + 4];
            float4 v4 = *(const float4*)&Vs[j][tx*4];
            float pv[8] = {p0.x,p0.y,p0.z,p0.w,p1.x,p1.y,p1.z,p1.w};
            float vv[4] = {v4.x,v4.y,v4.z,v4.w};
            #pragma unroll
            for (int i = 0; i < 8; i++)
                #pragma unroll
                for (int e = 0; e < 4; e++)
                    acc[i][e] = fmaf(pv[i], vv[e], acc[i][e]);
        }
    }

    // Write partial
    const int unit = ((b * 32 + qt) << 2) + s;
    float* Od = g_opart + (size_t)unit * 64 * 64;
    if (tx == 0) {
        #pragma unroll
        for (int i = 0; i < 8; i++) {
            g_mpart[unit*64 + ty*8 + i] = m[i];
            g_lpart[unit*64 + ty*8 + i] = l[i];
        }
    }
    #pragma unroll
    for (int i = 0; i < 8; i++) {
        float4 o4 = make_float4(acc[i][0], acc[i][1], acc[i][2], acc[i][3]);
        *(float4*)&Od[(ty*8 + i) * 64 + tx*4] = o4;
    }
}

// ---------------------------------------------------------------------------
// Combine partials + normalize + fused output projection.
// One block per (b, qt) = 256 blocks, 128 threads.
// ---------------------------------------------------------------------------
__global__ __launch_bounds__(128)
void combine_kernel(const float* __restrict__ W0, const float* __restrict__ b0,
                    float* __restrict__ out)
{
    __shared__ float scale_s[4][64];
    __shared__ float invl_s[64];
    __shared__ float Ot[64][TSTR];   // combined O^T: [e][i]
    __shared__ float Ws[64][TSTR];   // W0: [e][o]

    const int t  = threadIdx.x;
    const int tx = t & 15;
    const int ty = t >> 4;
    const int b  = blockIdx.x >> 5;
    const int qt = blockIdx.x & 31;
    const int ns = (qt >> 3) + 1;
    const int base = (b * 32 + qt) << 2;

    // Per-row stats merge (first 64 threads)
    if (t < 64) {
        float ms[4];
        float mm = -1e30f;
        for (int s = 0; s < ns; s++) {
            ms[s] = g_mpart[(base + s) * 64 + t];
            mm = fmaxf(mm, ms[s]);
        }
        float ll = 0.f;
        for (int s = 0; s < ns; s++) {
            float sc = __expf(ms[s] - mm);
            scale_s[s][t] = sc;
            ll += g_lpart[(base + s) * 64 + t] * sc;
        }
        invl_s[t] = 1.0f / ll;
    }
    // Load W0 while stats are being computed
    #pragma unroll
    for (int it = 0; it < 8; it++) {
        int idx = t + it * 128;
        int row = idx >> 4;
        int c   = (idx & 15) << 2;
        *(float4*)&Ws[row][c] = *(const float4*)&W0[row * 64 + c];
    }
    __syncthreads();

    // Combine O partials -> transposed smem (normalized)
    #pragma unroll
    for (int i = 0; i < 8; i++) {
        int row = ty * 8 + i;
        float4 v = make_float4(0.f, 0.f, 0.f, 0.f);
        for (int s = 0; s < ns; s++) {
            const float* Op = g_opart + (size_t)(base + s) * 4096;
            float4 o4 = *(const float4*)&Op[row * 64 + tx*4];
            float sc = scale_s[s][row];
            v.x = fmaf(o4.x, sc, v.x); v.y = fmaf(o4.y, sc, v.y);
            v.z = fmaf(o4.z, sc, v.z); v.w = fmaf(o4.w, sc, v.w);
        }
        float inv = invl_s[row];
        Ot[tx*4 + 0][row] = v.x * inv;
        Ot[tx*4 + 1][row] = v.y * inv;
        Ot[tx*4 + 2][row] = v.z * inv;
        Ot[tx*4 + 3][row] = v.w * inv;
    }
    __syncthreads();

    // out = O * W0 + b0
    float res[8][4];
    #pragma unroll
    for (int i = 0; i < 8; i++)
        #pragma unroll
        for (int j = 0; j < 4; j++) res[i][j] = 0.f;

    #pragma unroll 8
    for (int e = 0; e < 64; e++) {
        float4 a0 = *(const float4*)&Ot[e][ty*8];
        float4 a1 = *(const float4*)&Ot[e][ty*8 + 4];
        float4 w4 = *(const float4*)&Ws[e][tx*4];
        float av[8] = {a0.x,a0.y,a0.z,a0.w,a1.x,a1.y,a1.z,a1.w};
        float wv[4] = {w4.x,w4.y,w4.z,w4.w};
        #pragma unroll
        for (int i = 0; i < 8; i++)
            #pragma unroll
            for (int o = 0; o < 4; o++)
                res[i][o] = fmaf(av[i], wv[o], res[i][o]);
    }

    float4 bb = *(const float4*)&b0[tx*4];
    float bv4[4] = {bb.x, bb.y, bb.z, bb.w};
    #pragma unroll
    for (int i = 0; i < 8; i++) {
        float4 o4;
        o4.x = res[i][0] + bv4[0];
        o4.y = res[i][1] + bv4[1];
        o4.z = res[i][2] + bv4[2];
        o4.w = res[i][3] + bv4[3];
        *(float4*)&out[((size_t)b * SEQ + qt*64 + ty*8 + i) * DI + tx*4] = o4;
    }
}

// ---------------------------------------------------------------------------
extern "C" void kernel_launch(void* const* d_in, const int* in_sizes, int n_in,
                              void* d_out, int out_size)
{
    const float* X  = (const float*)d_in[0];
    const float* Wk = (const float*)d_in[1];
    const float* bk = (const float*)d_in[2];
    const float* Wq = (const float*)d_in[3];
    const float* bq = (const float*)d_in[4];
    const float* Wv = (const float*)d_in[5];
    const float* bv = (const float*)d_in[6];
    const float* W0 = (const float*)d_in[7];
    const float* b0 = (const float*)d_in[8];
    float* out = (float*)d_out;

    const int attn_smem = (3 * 64 * TSTR + 64 * 64) * (int)sizeof(float);  // 68608 B
    cudaFuncSetAttribute(attn_part_kernel, cudaFuncAttributeMaxDynamicSharedMemorySize,
                         attn_smem);

    dim3 pg(NB * SEQ / 128, 3);
    proj_kernel<<<pg, 256>>>(X, Wq, bq, Wk, bk, Wv, bv);
    attn_part_kernel<<<NB * 80, 128, attn_smem>>>();
    combine_kernel<<<NB * 32, 128>>>(W0, b0, out);
}

// round 5
// speedup vs baseline: 2.4189x; 2.0156x over previous
#include <cuda_runtime.h>
#include <cstdint>

#define SEQ 2048
#define DM  1024
#define DI  64
#define NB  8

__device__ float g_q[NB*SEQ*DI];
__device__ float g_k[NB*SEQ*DI];
__device__ float g_v[NB*SEQ*DI];

__device__ float g_opart[NB*32*4*64*64];
__device__ float g_mpart[NB*32*4*64];
__device__ float g_lpart[NB*32*4*64];

__device__ __forceinline__ uint32_t f2tf32(float x) {
    uint32_t r;
    asm("cvt.rna.tf32.f32 %0, %1;" : "=r"(r) : "f"(x));
    return r;
}

__device__ __forceinline__ void mma_tf32(float c[4],
    uint32_t a0, uint32_t a1, uint32_t a2, uint32_t a3,
    uint32_t b0, uint32_t b1)
{
    asm volatile(
        "mma.sync.aligned.m16n8k8.row.col.f32.tf32.tf32.f32 "
        "{%0,%1,%2,%3}, {%4,%5,%6,%7}, {%8,%9}, {%0,%1,%2,%3};"
        : "+f"(c[0]), "+f"(c[1]), "+f"(c[2]), "+f"(c[3])
        : "r"(a0), "r"(a1), "r"(a2), "r"(a3), "r"(b0), "r"(b1));
}

// ---------------------------------------------------------------------------
// QKV projection via tf32 MMA: C[16384x64] = X[16384x1024]*W[1024x64] + b
// 256 threads (8 warps), block tile 128x64, K-chunk 32. Warp w owns rows
// [w*16, w*16+16). Fragments gathered from smem laid out [row][k], stride 36
// (g*36+tig mod 32 distinct for all 32 lanes -> conflict-free).
// ---------------------------------------------------------------------------
__global__ __launch_bounds__(256)
void proj_kernel(const float* __restrict__ X,
                 const float* __restrict__ Wq, const float* __restrict__ bq,
                 const float* __restrict__ Wk, const float* __restrict__ bk,
                 const float* __restrict__ Wv, const float* __restrict__ bv)
{
    __shared__ uint32_t As[128][36];
    __shared__ uint32_t Bs[64][36];

    const float* W; const float* bi; float* dst; float scale = 1.0f;
    if (blockIdx.y == 0)      { W = Wq; bi = bq; dst = g_q; scale = 0.125f; }
    else if (blockIdx.y == 1) { W = Wk; bi = bk; dst = g_k; }
    else                      { W = Wv; bi = bv; dst = g_v; }

    const int t    = threadIdx.x;
    const int w    = t >> 5;
    const int lane = t & 31;
    const int g    = lane >> 2;
    const int tig  = lane & 3;
    const int m0   = w * 16;
    const size_t r0 = (size_t)blockIdx.x * 128;

    float c[8][4];
    #pragma unroll
    for (int n = 0; n < 8; n++)
        #pragma unroll
        for (int j = 0; j < 4; j++) c[n][j] = 0.f;

    for (int kb = 0; kb < DM; kb += 32) {
        // A tile 128x32
        #pragma unroll
        for (int it = 0; it < 4; it++) {
            int idx = t + it * 256;
            int row = idx >> 3;
            int c4  = (idx & 7) << 2;
            float4 a = *(const float4*)&X[(r0 + row) * DM + kb + c4];
            As[row][c4+0] = f2tf32(a.x); As[row][c4+1] = f2tf32(a.y);
            As[row][c4+2] = f2tf32(a.z); As[row][c4+3] = f2tf32(a.w);
        }
        // B tile 32x64, stored transposed Bs[n][k]
        #pragma unroll
        for (int it = 0; it < 2; it++) {
            int idx = t + it * 256;
            int k  = idx >> 4;
            int c4 = (idx & 15) << 2;
            float4 b = *(const float4*)&W[(size_t)(kb + k) * DI + c4];
            Bs[c4+0][k] = f2tf32(b.x); Bs[c4+1][k] = f2tf32(b.y);
            Bs[c4+2][k] = f2tf32(b.z); Bs[c4+3][k] = f2tf32(b.w);
        }
        __syncthreads();

        #pragma unroll
        for (int kk = 0; kk < 32; kk += 8) {
            uint32_t a0 = As[m0+g][kk+tig];
            uint32_t a1 = As[m0+g+8][kk+tig];
            uint32_t a2 = As[m0+g][kk+tig+4];
            uint32_t a3 = As[m0+g+8][kk+tig+4];
            #pragma unroll
            for (int n = 0; n < 8; n++) {
                uint32_t b0 = Bs[n*8+g][kk+tig];
                uint32_t b1 = Bs[n*8+g][kk+tig+4];
                mma_tf32(c[n], a0, a1, a2, a3, b0, b1);
            }
        }
        __syncthreads();
    }

    #pragma unroll
    for (int n = 0; n < 8; n++) {
        int col = n*8 + tig*2;
        float bv0 = bi[col], bv1 = bi[col+1];
        float2 o0 = make_float2((c[n][0] + bv0) * scale, (c[n][1] + bv1) * scale);
        float2 o1 = make_float2((c[n][2] + bv0) * scale, (c[n][3] + bv1) * scale);
        *(float2*)&dst[(r0 + m0 + g) * DI + col]     = o0;
        *(float2*)&dst[(r0 + m0 + g + 8) * DI + col] = o1;
    }
}

// ---------------------------------------------------------------------------
// Split-KV flash attention via tf32 MMA. 128 threads (4 warps), q-tile 64
// (warp owns 16 rows), kv split chunk = 8 tiles. S = Q K^T and O += P V both
// on tensor pipe; P round-trips smem in A-fragment layout.
// ---------------------------------------------------------------------------
#define AST  68
#define CHUNK 8

__global__ __launch_bounds__(128)
void attn_part_kernel()
{
    extern __shared__ uint32_t smu[];
    uint32_t (*Qs)[AST] = (uint32_t(*)[AST])(smu);             // Q[i][d]
    uint32_t (*Ks)[AST] = (uint32_t(*)[AST])(smu + 64*AST);    // K[j][d]
    uint32_t (*Vt)[AST] = (uint32_t(*)[AST])(smu + 2*64*AST);  // V^T[e][j]
    uint32_t (*Ps)[AST] = (uint32_t(*)[AST])(smu + 3*64*AST);  // P[i][j]

    const int t    = threadIdx.x;
    const int w    = t >> 5;
    const int lane = t & 31;
    const int g    = lane >> 2;
    const int tig  = lane & 3;
    const int m0   = w * 16;

    // Decode (b, qt, split)
    const int b = blockIdx.x / 80;
    int u = blockIdx.x % 80;
    int qt = 0, s = 0;
    #pragma unroll 1
    for (qt = 0; qt < 32; qt++) {
        int ns = (qt >> 3) + 1;
        if (u < ns) { s = u; break; }
        u -= ns;
    }
    const int q0  = qt * 64;
    const int jt0 = s * CHUNK;
    const int jt1 = min(jt0 + CHUNK, qt + 1);

    // Load Q tile (pre-scaled at projection) as tf32
    const float* qp = g_q + ((size_t)b * SEQ + q0) * DI;
    #pragma unroll
    for (int it = 0; it < 8; it++) {
        int idx = t + it * 128;
        int row = idx >> 4;
        int c4  = (idx & 15) << 2;
        float4 a = *(const float4*)&qp[row * DI + c4];
        Qs[row][c4+0] = f2tf32(a.x); Qs[row][c4+1] = f2tf32(a.y);
        Qs[row][c4+2] = f2tf32(a.z); Qs[row][c4+3] = f2tf32(a.w);
    }

    float m0r = -1e30f, m1r = -1e30f, l0r = 0.f, l1r = 0.f;
    float o[8][4];
    #pragma unroll
    for (int n = 0; n < 8; n++)
        #pragma unroll
        for (int j = 0; j < 4; j++) o[n][j] = 0.f;

    for (int jt = jt0; jt < jt1; jt++) {
        const float* kp = g_k + ((size_t)b * SEQ + jt * 64) * DI;
        const float* vp = g_v + ((size_t)b * SEQ + jt * 64) * DI;
        __syncthreads();
        #pragma unroll
        for (int it = 0; it < 8; it++) {
            int idx = t + it * 128;
            int row = idx >> 4;
            int c4  = (idx & 15) << 2;
            float4 kv = *(const float4*)&kp[row * DI + c4];
            Ks[row][c4+0] = f2tf32(kv.x); Ks[row][c4+1] = f2tf32(kv.y);
            Ks[row][c4+2] = f2tf32(kv.z); Ks[row][c4+3] = f2tf32(kv.w);
            float4 vv = *(const float4*)&vp[row * DI + c4];
            Vt[c4+0][row] = f2tf32(vv.x); Vt[c4+1][row] = f2tf32(vv.y);
            Vt[c4+2][row] = f2tf32(vv.z); Vt[c4+3][row] = f2tf32(vv.w);
        }
        __syncthreads();

        // S = Q K^T
        float sv[8][4];
        #pragma unroll
        for (int n = 0; n < 8; n++)
            #pragma unroll
            for (int j = 0; j < 4; j++) sv[n][j] = 0.f;

        #pragma unroll
        for (int kk = 0; kk < 64; kk += 8) {
            uint32_t a0 = Qs[m0+g][kk+tig];
            uint32_t a1 = Qs[m0+g+8][kk+tig];
            uint32_t a2 = Qs[m0+g][kk+tig+4];
            uint32_t a3 = Qs[m0+g+8][kk+tig+4];
            #pragma unroll
            for (int n = 0; n < 8; n++) {
                uint32_t b0 = Ks[n*8+g][kk+tig];
                uint32_t b1 = Ks[n*8+g][kk+tig+4];
                mma_tf32(sv[n], a0, a1, a2, a3, b0, b1);
            }
        }

        const int row0 = q0 + m0 + g;
        const int row1 = row0 + 8;
        if (jt == qt) {
            #pragma unroll
            for (int n = 0; n < 8; n++) {
                int col = jt*64 + n*8 + tig*2;
                if (col     > row0) sv[n][0] = -1e30f;
                if (col + 1 > row0) sv[n][1] = -1e30f;
                if (col     > row1) sv[n][2] = -1e30f;
                if (col + 1 > row1) sv[n][3] = -1e30f;
            }
        }

        // Online softmax: row0 via c0/c1, row1 via c2/c3; reduce in quad
        float mx0 = -1e30f, mx1 = -1e30f;
        #pragma unroll
        for (int n = 0; n < 8; n++) {
            mx0 = fmaxf(mx0, fmaxf(sv[n][0], sv[n][1]));
            mx1 = fmaxf(mx1, fmaxf(sv[n][2], sv[n][3]));
        }
        mx0 = fmaxf(mx0, __shfl_xor_sync(0xffffffffu, mx0, 1));
        mx0 = fmaxf(mx0, __shfl_xor_sync(0xffffffffu, mx0, 2));
        mx1 = fmaxf(mx1, __shfl_xor_sync(0xffffffffu, mx1, 1));
        mx1 = fmaxf(mx1, __shfl_xor_sync(0xffffffffu, mx1, 2));

        float nm0 = fmaxf(m0r, mx0), nm1 = fmaxf(m1r, mx1);
        float sc0 = __expf(m0r - nm0), sc1 = __expf(m1r - nm1);
        float rs0 = 0.f, rs1 = 0.f;
        #pragma unroll
        for (int n = 0; n < 8; n++) {
            float p00 = __expf(sv[n][0] - nm0);
            float p01 = __expf(sv[n][1] - nm0);
            float p10 = __expf(sv[n][2] - nm1);
            float p11 = __expf(sv[n][3] - nm1);
            rs0 += p00 + p01;
            rs1 += p10 + p11;
            int col = n*8 + tig*2;
            Ps[m0+g][col]     = f2tf32(p00);
            Ps[m0+g][col+1]   = f2tf32(p01);
            Ps[m0+g+8][col]   = f2tf32(p10);
            Ps[m0+g+8][col+1] = f2tf32(p11);
            o[n][0] *= sc0; o[n][1] *= sc0;
            o[n][2] *= sc1; o[n][3] *= sc1;
        }
        rs0 += __shfl_xor_sync(0xffffffffu, rs0, 1);
        rs0 += __shfl_xor_sync(0xffffffffu, rs0, 2);
        rs1 += __shfl_xor_sync(0xffffffffu, rs1, 1);
        rs1 += __shfl_xor_sync(0xffffffffu, rs1, 2);
        l0r = l0r * sc0 + rs0; m0r = nm0;
        l1r = l1r * sc1 + rs1; m1r = nm1;
        __syncwarp();

        // O += P V
        #pragma unroll
        for (int kk = 0; kk < 64; kk += 8) {
            uint32_t a0 = Ps[m0+g][kk+tig];
            uint32_t a1 = Ps[m0+g+8][kk+tig];
            uint32_t a2 = Ps[m0+g][kk+tig+4];
            uint32_t a3 = Ps[m0+g+8][kk+tig+4];
            #pragma unroll
            for (int n = 0; n < 8; n++) {
                uint32_t b0 = Vt[n*8+g][kk+tig];
                uint32_t b1 = Vt[n*8+g][kk+tig+4];
                mma_tf32(o[n], a0, a1, a2, a3, b0, b1);
            }
        }
    }

    // Emit unnormalized partial + stats
    const int unit = ((b * 32 + qt) << 2) + s;
    float* Od = g_opart + (size_t)unit * 4096;
    if (tig == 0) {
        g_mpart[unit*64 + m0 + g]     = m0r;
        g_lpart[unit*64 + m0 + g]     = l0r;
        g_mpart[unit*64 + m0 + g + 8] = m1r;
        g_lpart[unit*64 + m0 + g + 8] = l1r;
    }
    #pragma unroll
    for (int n = 0; n < 8; n++) {
        int col = n*8 + tig*2;
        *(float2*)&Od[(m0 + g) * 64 + col]     = make_float2(o[n][0], o[n][1]);
        *(float2*)&Od[(m0 + g + 8) * 64 + col] = make_float2(o[n][2], o[n][3]);
    }
}

// ---------------------------------------------------------------------------
// Combine partials + normalize + fused output projection (fp32).
// ---------------------------------------------------------------------------
#define TSTR 68

__global__ __launch_bounds__(128)
void combine_kernel(const float* __restrict__ W0, const float* __restrict__ b0,
                    float* __restrict__ out)
{
    __shared__ float scale_s[4][64];
    __shared__ float invl_s[64];
    __shared__ float Ot[64][TSTR];
    __shared__ float Ws[64][TSTR];

    const int t  = threadIdx.x;
    const int tx = t & 15;
    const int ty = t >> 4;
    const int b  = blockIdx.x >> 5;
    const int qt = blockIdx.x & 31;
    const int ns = (qt >> 3) + 1;
    const int base = (b * 32 + qt) << 2;

    if (t < 64) {
        float ms[4];
        float mm = -1e30f;
        for (int s = 0; s < ns; s++) {
            ms[s] = g_mpart[(base + s) * 64 + t];
            mm = fmaxf(mm, ms[s]);
        }
        float ll = 0.f;
        for (int s = 0; s < ns; s++) {
            float sc = __expf(ms[s] - mm);
            scale_s[s][t] = sc;
            ll += g_lpart[(base + s) * 64 + t] * sc;
        }
        invl_s[t] = 1.0f / ll;
    }
    #pragma unroll
    for (int it = 0; it < 8; it++) {
        int idx = t + it * 128;
        int row = idx >> 4;
        int c   = (idx & 15) << 2;
        *(float4*)&Ws[row][c] = *(const float4*)&W0[row * 64 + c];
    }
    __syncthreads();

    #pragma unroll
    for (int i = 0; i < 8; i++) {
        int row = ty * 8 + i;
        float4 v = make_float4(0.f, 0.f, 0.f, 0.f);
        for (int s = 0; s < ns; s++) {
            const float* Op = g_opart + (size_t)(base + s) * 4096;
            float4 o4 = *(const float4*)&Op[row * 64 + tx*4];
            float sc = scale_s[s][row];
            v.x = fmaf(o4.x, sc, v.x); v.y = fmaf(o4.y, sc, v.y);
            v.z = fmaf(o4.z, sc, v.z); v.w = fmaf(o4.w, sc, v.w);
        }
        float inv = invl_s[row];
        Ot[tx*4 + 0][row] = v.x * inv;
        Ot[tx*4 + 1][row] = v.y * inv;
        Ot[tx*4 + 2][row] = v.z * inv;
        Ot[tx*4 + 3][row] = v.w * inv;
    }
    __syncthreads();

    float res[8][4];
    #pragma unroll
    for (int i = 0; i < 8; i++)
        #pragma unroll
        for (int j = 0; j < 4; j++) res[i][j] = 0.f;

    #pragma unroll 8
    for (int e = 0; e < 64; e++) {
        float4 a0 = *(const float4*)&Ot[e][ty*8];
        float4 a1 = *(const float4*)&Ot[e][ty*8 + 4];
        float4 w4 = *(const float4*)&Ws[e][tx*4];
        float av[8] = {a0.x,a0.y,a0.z,a0.w,a1.x,a1.y,a1.z,a1.w};
        float wv[4] = {w4.x,w4.y,w4.z,w4.w};
        #pragma unroll
        for (int i = 0; i < 8; i++)
            #pragma unroll
            for (int o2 = 0; o2 < 4; o2++)
                res[i][o2] = fmaf(av[i], wv[o2], res[i][o2]);
    }

    float4 bb = *(const float4*)&b0[tx*4];
    float bv4[4] = {bb.x, bb.y, bb.z, bb.w};
    #pragma unroll
    for (int i = 0; i < 8; i++) {
        float4 o4;
        o4.x = res[i][0] + bv4[0];
        o4.y = res[i][1] + bv4[1];
        o4.z = res[i][2] + bv4[2];
        o4.w = res[i][3] + bv4[3];
        *(float4*)&out[((size_t)b * SEQ + qt*64 + ty*8 + i) * DI + tx*4] = o4;
    }
}

// ---------------------------------------------------------------------------
extern "C" void kernel_launch(void* const* d_in, const int* in_sizes, int n_in,
                              void* d_out, int out_size)
{
    const float* X  = (const float*)d_in[0];
    const float* Wk = (const float*)d_in[1];
    const float* bk = (const float*)d_in[2];
    const float* Wq = (const float*)d_in[3];
    const float* bq = (const float*)d_in[4];
    const float* Wv = (const float*)d_in[5];
    const float* bv = (const float*)d_in[6];
    const float* W0 = (const float*)d_in[7];
    const float* b0 = (const float*)d_in[8];
    float* out = (float*)d_out;

    const int attn_smem = 4 * 64 * AST * (int)sizeof(uint32_t);  // 69632 B
    cudaFuncSetAttribute(attn_part_kernel, cudaFuncAttributeMaxDynamicSharedMemorySize,
                         attn_smem);

    dim3 pg(NB * SEQ / 128, 3);
    proj_kernel<<<pg, 256>>>(X, Wq, bq, Wk, bk, Wv, bv);
    attn_part_kernel<<<NB * 80, 128, attn_smem>>>();
    combine_kernel<<<NB * 32, 128>>>(W0, b0, out);
}

// round 6
// speedup vs baseline: 3.3116x; 1.3691x over previous
#include <cuda_runtime.h>
#include <cstdint>

#define SEQ 2048
#define DM  1024
#define DI  64
#define NB  8

__device__ float g_q[NB*SEQ*DI];
__device__ float g_k[NB*SEQ*DI];
__device__ float g_v[NB*SEQ*DI];

// Split partials: q-tile=128 rows, up to 4 splits. unit = (b*16+qt)*4+s
__device__ float g_opart[NB*16*4*128*64];
__device__ float g_mpart[NB*16*4*128];
__device__ float g_lpart[NB*16*4*128];

__device__ __forceinline__ uint32_t f2tf32(float x) {
    uint32_t r;
    asm("cvt.rna.tf32.f32 %0, %1;" : "=r"(r) : "f"(x));
    return r;
}

__device__ __forceinline__ void mma_tf32(float c[4],
    uint32_t a0, uint32_t a1, uint32_t a2, uint32_t a3,
    uint32_t b0, uint32_t b1)
{
    asm volatile(
        "mma.sync.aligned.m16n8k8.row.col.f32.tf32.tf32.f32 "
        "{%0,%1,%2,%3}, {%4,%5,%6,%7}, {%8,%9}, {%0,%1,%2,%3};"
        : "+f"(c[0]), "+f"(c[1]), "+f"(c[2]), "+f"(c[3])
        : "r"(a0), "r"(a1), "r"(a2), "r"(a3), "r"(b0), "r"(b1));
}

// ---------------------------------------------------------------------------
// QKV projection: 128 threads (4 warps), block tile 128x64, K-chunk 32.
// Warp owns m32 x n64 (Mt=2, Nt=8). Global loads software-pipelined.
// A smem [row][k] stride 36 (reads: bank 4g+tig, conflict-free).
// B smem [k][n] stride 72 (reads: bank 8tig+8n+g, conflict-free; uint4 stores).
// ---------------------------------------------------------------------------
__global__ __launch_bounds__(128)
void proj_kernel(const float* __restrict__ X,
                 const float* __restrict__ Wq, const float* __restrict__ bq,
                 const float* __restrict__ Wk, const float* __restrict__ bk,
                 const float* __restrict__ Wv, const float* __restrict__ bv)
{
    __shared__ uint32_t As[128][36];
    __shared__ uint32_t Bs[32][72];

    const float* W; const float* bi; float* dst; float scale = 1.0f;
    if (blockIdx.y == 0)      { W = Wq; bi = bq; dst = g_q; scale = 0.125f; }
    else if (blockIdx.y == 1) { W = Wk; bi = bk; dst = g_k; }
    else                      { W = Wv; bi = bv; dst = g_v; }

    const int t    = threadIdx.x;
    const int w    = t >> 5;
    const int lane = t & 31;
    const int g    = lane >> 2;
    const int tig  = lane & 3;
    const int m0   = w * 32;
    const size_t r0 = (size_t)blockIdx.x * 128;

    float4 ra[8], rb[4];
    #pragma unroll
    for (int it = 0; it < 8; it++) {
        int idx = t + it * 128;
        ra[it] = *(const float4*)&X[(r0 + (idx >> 3)) * DM + ((idx & 7) << 2)];
    }
    #pragma unroll
    for (int it = 0; it < 4; it++) {
        int idx = t + it * 128;
        rb[it] = *(const float4*)&W[(size_t)(idx >> 4) * DI + ((idx & 15) << 2)];
    }

    float c[2][8][4];
    #pragma unroll
    for (int mt = 0; mt < 2; mt++)
        #pragma unroll
        for (int n = 0; n < 8; n++)
            #pragma unroll
            for (int j = 0; j < 4; j++) c[mt][n][j] = 0.f;

    for (int kb = 0; kb < DM; kb += 32) {
        #pragma unroll
        for (int it = 0; it < 8; it++) {
            int idx = t + it * 128;
            uint4 u = make_uint4(f2tf32(ra[it].x), f2tf32(ra[it].y),
                                 f2tf32(ra[it].z), f2tf32(ra[it].w));
            *(uint4*)&As[idx >> 3][(idx & 7) << 2] = u;
        }
        #pragma unroll
        for (int it = 0; it < 4; it++) {
            int idx = t + it * 128;
            uint4 u = make_uint4(f2tf32(rb[it].x), f2tf32(rb[it].y),
                                 f2tf32(rb[it].z), f2tf32(rb[it].w));
            *(uint4*)&Bs[idx >> 4][(idx & 15) << 2] = u;
        }
        __syncthreads();

        if (kb + 32 < DM) {  // prefetch next chunk (overlaps with mma below)
            #pragma unroll
            for (int it = 0; it < 8; it++) {
                int idx = t + it * 128;
                ra[it] = *(const float4*)&X[(r0 + (idx >> 3)) * DM + kb + 32 + ((idx & 7) << 2)];
            }
            #pragma unroll
            for (int it = 0; it < 4; it++) {
                int idx = t + it * 128;
                rb[it] = *(const float4*)&W[(size_t)(kb + 32 + (idx >> 4)) * DI + ((idx & 15) << 2)];
            }
        }

        #pragma unroll
        for (int kk = 0; kk < 32; kk += 8) {
            uint32_t a[2][4];
            #pragma unroll
            for (int mt = 0; mt < 2; mt++) {
                int r = m0 + mt * 16 + g;
                a[mt][0] = As[r][kk + tig];
                a[mt][1] = As[r + 8][kk + tig];
                a[mt][2] = As[r][kk + tig + 4];
                a[mt][3] = As[r + 8][kk + tig + 4];
            }
            #pragma unroll
            for (int n = 0; n < 8; n++) {
                uint32_t b0 = Bs[kk + tig][n*8 + g];
                uint32_t b1 = Bs[kk + tig + 4][n*8 + g];
                mma_tf32(c[0][n], a[0][0], a[0][1], a[0][2], a[0][3], b0, b1);
                mma_tf32(c[1][n], a[1][0], a[1][1], a[1][2], a[1][3], b0, b1);
            }
        }
        __syncthreads();
    }

    #pragma unroll
    for (int mt = 0; mt < 2; mt++)
        #pragma unroll
        for (int n = 0; n < 8; n++) {
            int col = n*8 + tig*2;
            float bv0 = bi[col], bv1 = bi[col+1];
            size_t rr = r0 + m0 + mt*16 + g;
            *(float2*)&dst[rr * DI + col] =
                make_float2((c[mt][n][0] + bv0) * scale, (c[mt][n][1] + bv1) * scale);
            *(float2*)&dst[(rr + 8) * DI + col] =
                make_float2((c[mt][n][2] + bv0) * scale, (c[mt][n][3] + bv1) * scale);
        }
}

// ---------------------------------------------------------------------------
// Split-KV flash attention. q-tile 128 (8 warps x m16), kv tile 64,
// split chunk = 8 kv tiles => 40 units/batch, 320 blocks of 256 threads.
// K/V global loads software-pipelined; V in natural [j][e] layout (stride 72).
// ---------------------------------------------------------------------------
#define AST  68
#define VST  72

__global__ __launch_bounds__(256)
void attn_part_kernel()
{
    extern __shared__ uint32_t smu[];
    uint32_t (*Qs)[AST] = (uint32_t(*)[AST])(smu);                        // Q[i][d]
    uint32_t (*Ks)[AST] = (uint32_t(*)[AST])(smu + 128*AST);              // K[j][d]
    uint32_t (*Vs)[VST] = (uint32_t(*)[VST])(smu + 128*AST + 64*AST);     // V[j][e]
    uint32_t (*Ps)[AST] = (uint32_t(*)[AST])(smu + 128*AST + 64*AST + 64*VST); // P[i][j]

    const int t    = threadIdx.x;
    const int w    = t >> 5;
    const int lane = t & 31;
    const int g    = lane >> 2;
    const int tig  = lane & 3;
    const int m0   = w * 16;

    // Decode (b, qt, s): 40 units per batch, qt in [0,16), chunk=8 kv tiles
    const int b = blockIdx.x / 40;
    int u = blockIdx.x % 40;
    int qt = 0, s = 0;
    #pragma unroll 1
    for (qt = 0; qt < 16; qt++) {
        int ns = ((2*qt + 1) >> 3) + 1;
        if (u < ns) { s = u; break; }
        u -= ns;
    }
    const int q0  = qt * 128;
    const int jt0 = s * 8;
    const int jt1 = min(jt0 + 8, 2*qt + 2);

    // Load Q tile (pre-scaled) as tf32
    const float* qp = g_q + ((size_t)b * SEQ + q0) * DI;
    #pragma unroll
    for (int it = 0; it < 8; it++) {
        int idx = t + it * 256;
        int row = idx >> 4;
        int c4  = (idx & 15) << 2;
        float4 a = *(const float4*)&qp[row * DI + c4];
        *(uint4*)&Qs[row][c4] = make_uint4(f2tf32(a.x), f2tf32(a.y),
                                           f2tf32(a.z), f2tf32(a.w));
    }

    // Prefetch first K/V tile into registers
    float4 rk[4], rv[4];
    {
        const float* kp = g_k + ((size_t)b * SEQ + jt0 * 64) * DI;
        const float* vp = g_v + ((size_t)b * SEQ + jt0 * 64) * DI;
        #pragma unroll
        for (int it = 0; it < 4; it++) {
            int idx = t + it * 256;
            int off = (idx >> 4) * DI + ((idx & 15) << 2);
            rk[it] = *(const float4*)&kp[off];
            rv[it] = *(const float4*)&vp[off];
        }
    }

    float m0r = -1e30f, m1r = -1e30f, l0r = 0.f, l1r = 0.f;
    float o[8][4];
    #pragma unroll
    for (int n = 0; n < 8; n++)
        #pragma unroll
        for (int j = 0; j < 4; j++) o[n][j] = 0.f;

    for (int jt = jt0; jt < jt1; jt++) {
        __syncthreads();   // prior tile's mma reads complete (also covers Q store)
        #pragma unroll
        for (int it = 0; it < 4; it++) {
            int idx = t + it * 256;
            int row = idx >> 4;
            int c4  = (idx & 15) << 2;
            *(uint4*)&Ks[row][c4] = make_uint4(f2tf32(rk[it].x), f2tf32(rk[it].y),
                                               f2tf32(rk[it].z), f2tf32(rk[it].w));
            *(uint4*)&Vs[row][c4] = make_uint4(f2tf32(rv[it].x), f2tf32(rv[it].y),
                                               f2tf32(rv[it].z), f2tf32(rv[it].w));
        }
        __syncthreads();

        if (jt + 1 < jt1) {  // prefetch next K/V tile
            const float* kp = g_k + ((size_t)b * SEQ + (jt+1) * 64) * DI;
            const float* vp = g_v + ((size_t)b * SEQ + (jt+1) * 64) * DI;
            #pragma unroll
            for (int it = 0; it < 4; it++) {
                int idx = t + it * 256;
                int off = (idx >> 4) * DI + ((idx & 15) << 2);
                rk[it] = *(const float4*)&kp[off];
                rv[it] = *(const float4*)&vp[off];
            }
        }

        // S = Q K^T
        float sv[8][4];
        #pragma unroll
        for (int n = 0; n < 8; n++)
            #pragma unroll
            for (int j = 0; j < 4; j++) sv[n][j] = 0.f;

        #pragma unroll
        for (int kk = 0; kk < 64; kk += 8) {
            uint32_t a0 = Qs[m0+g][kk+tig];
            uint32_t a1 = Qs[m0+g+8][kk+tig];
            uint32_t a2 = Qs[m0+g][kk+tig+4];
            uint32_t a3 = Qs[m0+g+8][kk+tig+4];
            #pragma unroll
            for (int n = 0; n < 8; n++) {
                uint32_t b0 = Ks[n*8+g][kk+tig];
                uint32_t b1 = Ks[n*8+g][kk+tig+4];
                mma_tf32(sv[n], a0, a1, a2, a3, b0, b1);
            }
        }

        const int row0 = q0 + m0 + g;
        const int row1 = row0 + 8;
        if (jt >= 2*qt) {  // tiles that can intersect the diagonal
            #pragma unroll
            for (int n = 0; n < 8; n++) {
                int col = jt*64 + n*8 + tig*2;
                if (col     > row0) sv[n][0] = -1e30f;
                if (col + 1 > row0) sv[n][1] = -1e30f;
                if (col     > row1) sv[n][2] = -1e30f;
                if (col + 1 > row1) sv[n][3] = -1e30f;
            }
        }

        // Online softmax (2 rows/lane, quad reduce)
        float mx0 = -1e30f, mx1 = -1e30f;
        #pragma unroll
        for (int n = 0; n < 8; n++) {
            mx0 = fmaxf(mx0, fmaxf(sv[n][0], sv[n][1]));
            mx1 = fmaxf(mx1, fmaxf(sv[n][2], sv[n][3]));
        }
        mx0 = fmaxf(mx0, __shfl_xor_sync(0xffffffffu, mx0, 1));
        mx0 = fmaxf(mx0, __shfl_xor_sync(0xffffffffu, mx0, 2));
        mx1 = fmaxf(mx1, __shfl_xor_sync(0xffffffffu, mx1, 1));
        mx1 = fmaxf(mx1, __shfl_xor_sync(0xffffffffu, mx1, 2));

        float nm0 = fmaxf(m0r, mx0), nm1 = fmaxf(m1r, mx1);
        float sc0 = __expf(m0r - nm0), sc1 = __expf(m1r - nm1);
        float rs0 = 0.f, rs1 = 0.f;
        #pragma unroll
        for (int n = 0; n < 8; n++) {
            float p00 = __expf(sv[n][0] - nm0);
            float p01 = __expf(sv[n][1] - nm0);
            float p10 = __expf(sv[n][2] - nm1);
            float p11 = __expf(sv[n][3] - nm1);
            rs0 += p00 + p01;
            rs1 += p10 + p11;
            int col = n*8 + tig*2;
            *(uint2*)&Ps[m0+g][col]   = make_uint2(f2tf32(p00), f2tf32(p01));
            *(uint2*)&Ps[m0+g+8][col] = make_uint2(f2tf32(p10), f2tf32(p11));
            o[n][0] *= sc0; o[n][1] *= sc0;
            o[n][2] *= sc1; o[n][3] *= sc1;
        }
        rs0 += __shfl_xor_sync(0xffffffffu, rs0, 1);
        rs0 += __shfl_xor_sync(0xffffffffu, rs0, 2);
        rs1 += __shfl_xor_sync(0xffffffffu, rs1, 1);
        rs1 += __shfl_xor_sync(0xffffffffu, rs1, 2);
        l0r = l0r * sc0 + rs0; m0r = nm0;
        l1r = l1r * sc1 + rs1; m1r = nm1;
        __syncwarp();   // Ps rows are warp-private

        // O += P V
        #pragma unroll
        for (int kk = 0; kk < 64; kk += 8) {
            uint32_t a0 = Ps[m0+g][kk+tig];
            uint32_t a1 = Ps[m0+g+8][kk+tig];
            uint32_t a2 = Ps[m0+g][kk+tig+4];
            uint32_t a3 = Ps[m0+g+8][kk+tig+4];
            #pragma unroll
            for (int n = 0; n < 8; n++) {
                uint32_t b0 = Vs[kk+tig][n*8+g];
                uint32_t b1 = Vs[kk+tig+4][n*8+g];
                mma_tf32(o[n], a0, a1, a2, a3, b0, b1);
            }
        }
    }

    // Emit unnormalized partial + stats
    const int unit = ((b * 16 + qt) << 2) + s;
    float* Od = g_opart + (size_t)unit * 128 * 64;
    if (tig == 0) {
        g_mpart[unit*128 + m0 + g]     = m0r;
        g_lpart[unit*128 + m0 + g]     = l0r;
        g_mpart[unit*128 + m0 + g + 8] = m1r;
        g_lpart[unit*128 + m0 + g + 8] = l1r;
    }
    #pragma unroll
    for (int n = 0; n < 8; n++) {
        int col = n*8 + tig*2;
        *(float2*)&Od[(m0 + g) * 64 + col]     = make_float2(o[n][0], o[n][1]);
        *(float2*)&Od[(m0 + g + 8) * 64 + col] = make_float2(o[n][2], o[n][3]);
    }
}

// ---------------------------------------------------------------------------
// Combine partials + normalize + fused output projection.
// One block per (b, qt, half64) = 256 blocks, 128 threads.
// ---------------------------------------------------------------------------
#define TSTR 68

__global__ __launch_bounds__(128)
void combine_kernel(const float* __restrict__ W0, const float* __restrict__ b0,
                    float* __restrict__ out)
{
    __shared__ float scale_s[4][64];
    __shared__ float invl_s[64];
    __shared__ float Ot[64][TSTR];
    __shared__ float Ws[64][TSTR];

    const int t    = threadIdx.x;
    const int tx   = t & 15;
    const int ty   = t >> 4;
    const int b    = blockIdx.x >> 5;
    const int qh   = blockIdx.x & 31;
    const int qt   = qh >> 1;
    const int half = qh & 1;
    const int ro   = half * 64;
    const int ns   = ((2*qt + 1) >> 3) + 1;
    const int base = (b * 16 + qt) << 2;

    if (t < 64) {
        float ms[4];
        float mm = -1e30f;
        for (int s = 0; s < ns; s++) {
            ms[s] = g_mpart[(base + s) * 128 + ro + t];
            mm = fmaxf(mm, ms[s]);
        }
        float ll = 0.f;
        for (int s = 0; s < ns; s++) {
            float sc = __expf(ms[s] - mm);
            scale_s[s][t] = sc;
            ll += g_lpart[(base + s) * 128 + ro + t] * sc;
        }
        invl_s[t] = 1.0f / ll;
    }
    #pragma unroll
    for (int it = 0; it < 8; it++) {
        int idx = t + it * 128;
        int row = idx >> 4;
        int c   = (idx & 15) << 2;
        *(float4*)&Ws[row][c] = *(const float4*)&W0[row * 64 + c];
    }
    __syncthreads();

    #pragma unroll
    for (int i = 0; i < 8; i++) {
        int row = ty * 8 + i;
        float4 v = make_float4(0.f, 0.f, 0.f, 0.f);
        for (int s = 0; s < ns; s++) {
            const float* Op = g_opart + (size_t)(base + s) * 8192;
            float4 o4 = *(const float4*)&Op[(ro + row) * 64 + tx*4];
            float sc = scale_s[s][row];
            v.x = fmaf(o4.x, sc, v.x); v.y = fmaf(o4.y, sc, v.y);
            v.z = fmaf(o4.z, sc, v.z); v.w = fmaf(o4.w, sc, v.w);
        }
        float inv = invl_s[row];
        Ot[tx*4 + 0][row] = v.x * inv;
        Ot[tx*4 + 1][row] = v.y * inv;
        Ot[tx*4 + 2][row] = v.z * inv;
        Ot[tx*4 + 3][row] = v.w * inv;
    }
    __syncthreads();

    float res[8][4];
    #pragma unroll
    for (int i = 0; i < 8; i++)
        #pragma unroll
        for (int j = 0; j < 4; j++) res[i][j] = 0.f;

    #pragma unroll 8
    for (int e = 0; e < 64; e++) {
        float4 a0 = *(const float4*)&Ot[e][ty*8];
        float4 a1 = *(const float4*)&Ot[e][ty*8 + 4];
        float4 w4 = *(const float4*)&Ws[e][tx*4];
        float av[8] = {a0.x,a0.y,a0.z,a0.w,a1.x,a1.y,a1.z,a1.w};
        float wv[4] = {w4.x,w4.y,w4.z,w4.w};
        #pragma unroll
        for (int i = 0; i < 8; i++)
            #pragma unroll
            for (int o2 = 0; o2 < 4; o2++)
                res[i][o2] = fmaf(av[i], wv[o2], res[i][o2]);
    }

    float4 bb = *(const float4*)&b0[tx*4];
    float bv4[4] = {bb.x, bb.y, bb.z, bb.w};
    #pragma unroll
    for (int i = 0; i < 8; i++) {
        float4 o4;
        o4.x = res[i][0] + bv4[0];
        o4.y = res[i][1] + bv4[1];
        o4.z = res[i][2] + bv4[2];
        o4.w = res[i][3] + bv4[3];
        *(float4*)&out[((size_t)b * SEQ + qt*128 + ro + ty*8 + i) * DI + tx*4] = o4;
    }
}

// ---------------------------------------------------------------------------
extern "C" void kernel_launch(void* const* d_in, const int* in_sizes, int n_in,
                              void* d_out, int out_size)
{
    const float* X  = (const float*)d_in[0];
    const float* Wk = (const float*)d_in[1];
    const float* bk = (const float*)d_in[2];
    const float* Wq = (const float*)d_in[3];
    const float* bq = (const float*)d_in[4];
    const float* Wv = (const float*)d_in[5];
    const float* bv = (const float*)d_in[6];
    const float* W0 = (const float*)d_in[7];
    const float* b0 = (const float*)d_in[8];
    float* out = (float*)d_out;

    const int attn_smem = (128*AST + 64*AST + 64*VST + 128*AST) * (int)sizeof(uint32_t);
    cudaFuncSetAttribute(attn_part_kernel, cudaFuncAttributeMaxDynamicSharedMemorySize,
                         attn_smem);

    dim3 pg(NB * SEQ / 128, 3);
    proj_kernel<<<pg, 128>>>(X, Wq, bq, Wk, bk, Wv, bv);
    attn_part_kernel<<<NB * 40, 256, attn_smem>>>();
    combine_kernel<<<NB * 32, 128>>>(W0, b0, out);
}

// round 7
// speedup vs baseline: 3.4176x; 1.0320x over previous
#include <cuda_runtime.h>
#include <cstdint>

#define SEQ 2048
#define DM  1024
#define DI  64
#define NB  8

__device__ float g_q[NB*SEQ*DI];   // stored pre-rounded to tf32, Q pre-scaled by 1/8
__device__ float g_k[NB*SEQ*DI];
__device__ float g_v[NB*SEQ*DI];

// Split partials: q-tile=128 rows, up to 4 splits. unit = (b*16+qt)*4+s
__device__ float g_opart[NB*16*4*128*64];
__device__ float g_mpart[NB*16*4*128];
__device__ float g_lpart[NB*16*4*128];

__device__ __forceinline__ uint32_t f2tf32(float x) {
    uint32_t r;
    asm("cvt.rna.tf32.f32 %0, %1;" : "=r"(r) : "f"(x));
    return r;
}
__device__ __forceinline__ float rnd_tf32(float x) {
    return __uint_as_float(f2tf32(x));
}

__device__ __forceinline__ void mma_tf32(float c[4],
    uint32_t a0, uint32_t a1, uint32_t a2, uint32_t a3,
    uint32_t b0, uint32_t b1)
{
    asm volatile(
        "mma.sync.aligned.m16n8k8.row.col.f32.tf32.tf32.f32 "
        "{%0,%1,%2,%3}, {%4,%5,%6,%7}, {%8,%9}, {%0,%1,%2,%3};"
        : "+f"(c[0]), "+f"(c[1]), "+f"(c[2]), "+f"(c[3])
        : "r"(a0), "r"(a1), "r"(a2), "r"(a3), "r"(b0), "r"(b1));
}

__device__ __forceinline__ void cpa16(uint32_t dst, const void* src) {
    asm volatile("cp.async.ca.shared.global [%0], [%1], 16;" :: "r"(dst), "l"(src));
}
__device__ __forceinline__ void cpa_commit() {
    asm volatile("cp.async.commit_group;");
}
template<int N> __device__ __forceinline__ void cpa_wait() {
    asm volatile("cp.async.wait_group %0;" :: "n"(N));
}

// ---------------------------------------------------------------------------
// QKV projection: 256 threads (8 warps: 4 row-groups x 2 col-groups),
// block tile 128x64, warp tile m32 x n32, K-chunk 32, register-staged
// prefetch with rna tf32 conversion. Outputs stored tf32-rounded.
// ---------------------------------------------------------------------------
__global__ __launch_bounds__(256)
void proj_kernel(const float* __restrict__ X,
                 const float* __restrict__ Wq, const float* __restrict__ bq,
                 const float* __restrict__ Wk, const float* __restrict__ bk,
                 const float* __restrict__ Wv, const float* __restrict__ bv)
{
    __shared__ uint32_t As[128][36];   // [row][k], reads bank 4g+tig: conflict-free
    __shared__ uint32_t Bs[32][72];    // [k][n],   reads bank 8tig+8n+g: conflict-free

    const float* W; const float* bi; float* dst; float scale = 1.0f;
    if (blockIdx.y == 0)      { W = Wq; bi = bq; dst = g_q; scale = 0.125f; }
    else if (blockIdx.y == 1) { W = Wk; bi = bk; dst = g_k; }
    else                      { W = Wv; bi = bv; dst = g_v; }

    const int t    = threadIdx.x;
    const int w    = t >> 5;
    const int wr   = w & 3;        // row group: m32
    const int wc   = w >> 2;       // col group: n32
    const int lane = t & 31;
    const int g    = lane >> 2;
    const int tig  = lane & 3;
    const int m0   = wr * 32;
    const int n0   = wc * 32;
    const size_t r0 = (size_t)blockIdx.x * 128;

    float4 ra[4], rb[2];
    #pragma unroll
    for (int it = 0; it < 4; it++) {
        int idx = t + it * 256;
        ra[it] = *(const float4*)&X[(r0 + (idx >> 3)) * DM + ((idx & 7) << 2)];
    }
    #pragma unroll
    for (int it = 0; it < 2; it++) {
        int idx = t + it * 256;
        rb[it] = *(const float4*)&W[(size_t)(idx >> 4) * DI + ((idx & 15) << 2)];
    }

    float c[2][4][4];
    #pragma unroll
    for (int mt = 0; mt < 2; mt++)
        #pragma unroll
        for (int n = 0; n < 4; n++)
            #pragma unroll
            for (int j = 0; j < 4; j++) c[mt][n][j] = 0.f;

    for (int kb = 0; kb < DM; kb += 32) {
        #pragma unroll
        for (int it = 0; it < 4; it++) {
            int idx = t + it * 256;
            *(uint4*)&As[idx >> 3][(idx & 7) << 2] =
                make_uint4(f2tf32(ra[it].x), f2tf32(ra[it].y),
                           f2tf32(ra[it].z), f2tf32(ra[it].w));
        }
        #pragma unroll
        for (int it = 0; it < 2; it++) {
            int idx = t + it * 256;
            *(uint4*)&Bs[idx >> 4][(idx & 15) << 2] =
                make_uint4(f2tf32(rb[it].x), f2tf32(rb[it].y),
                           f2tf32(rb[it].z), f2tf32(rb[it].w));
        }
        __syncthreads();

        if (kb + 32 < DM) {  // prefetch next chunk, overlaps with mma below
            #pragma unroll
            for (int it = 0; it < 4; it++) {
                int idx = t + it * 256;
                ra[it] = *(const float4*)&X[(r0 + (idx >> 3)) * DM + kb + 32 + ((idx & 7) << 2)];
            }
            #pragma unroll
            for (int it = 0; it < 2; it++) {
                int idx = t + it * 256;
                rb[it] = *(const float4*)&W[(size_t)(kb + 32 + (idx >> 4)) * DI + ((idx & 15) << 2)];
            }
        }

        #pragma unroll
        for (int kk = 0; kk < 32; kk += 8) {
            uint32_t a[2][4];
            #pragma unroll
            for (int mt = 0; mt < 2; mt++) {
                int r = m0 + mt * 16 + g;
                a[mt][0] = As[r][kk + tig];
                a[mt][1] = As[r + 8][kk + tig];
                a[mt][2] = As[r][kk + tig + 4];
                a[mt][3] = As[r + 8][kk + tig + 4];
            }
            #pragma unroll
            for (int n = 0; n < 4; n++) {
                uint32_t b0 = Bs[kk + tig][n0 + n*8 + g];
                uint32_t b1 = Bs[kk + tig + 4][n0 + n*8 + g];
                mma_tf32(c[0][n], a[0][0], a[0][1], a[0][2], a[0][3], b0, b1);
                mma_tf32(c[1][n], a[1][0], a[1][1], a[1][2], a[1][3], b0, b1);
            }
        }
        __syncthreads();
    }

    #pragma unroll
    for (int mt = 0; mt < 2; mt++)
        #pragma unroll
        for (int n = 0; n < 4; n++) {
            int col = n0 + n*8 + tig*2;
            float bv0 = bi[col], bv1 = bi[col+1];
            size_t rr = r0 + m0 + mt*16 + g;
            *(float2*)&dst[rr * DI + col] =
                make_float2(rnd_tf32((c[mt][n][0] + bv0) * scale),
                            rnd_tf32((c[mt][n][1] + bv1) * scale));
            *(float2*)&dst[(rr + 8) * DI + col] =
                make_float2(rnd_tf32((c[mt][n][2] + bv0) * scale),
                            rnd_tf32((c[mt][n][3] + bv1) * scale));
        }
}

// ---------------------------------------------------------------------------
// Split-KV flash attention. q-tile 128 (8 warps x m16), kv tile 64,
// chunk = 8 kv tiles => 40 units/batch, 320 blocks x 256 threads.
// K/V double-buffered via cp.async. No P smem round-trip: P A-fragments
// built from the S fragment with 2-shfl column exchange.
// smem = Qs(128x68) + 2xKs(64x68) + 2xVs(64x72) = 106496 B -> 2 blocks/SM.
// ---------------------------------------------------------------------------
#define QST 68
#define KST 68
#define VST 72
#define OFF_K 8704
#define OFF_V 17408

__global__ __launch_bounds__(256)
void attn_part_kernel()
{
    extern __shared__ uint32_t smu[];
    uint32_t (*Qs)[QST] = (uint32_t(*)[QST])(smu);
    const uint32_t sb = (uint32_t)__cvta_generic_to_shared(smu);

    const int t    = threadIdx.x;
    const int lane = t & 31;
    const int g    = lane >> 2;
    const int tig  = lane & 3;
    const int m0   = (t >> 5) * 16;

    // Decode (b, qt, s): 40 units per batch, qt in [0,16), chunk = 8 kv tiles
    const int b = blockIdx.x / 40;
    int u = blockIdx.x % 40;
    int qt = 0, s = 0;
    #pragma unroll 1
    for (qt = 0; qt < 16; qt++) {
        int ns = ((2*qt + 1) >> 3) + 1;
        if (u < ns) { s = u; break; }
        u -= ns;
    }
    const int q0  = qt * 128;
    const int jt0 = s * 8;
    const int jt1 = min(jt0 + 8, 2*qt + 2);

    // Load Q tile (pre-rounded tf32, pre-scaled): raw bit copy
    const float* qp = g_q + ((size_t)b * SEQ + q0) * DI;
    #pragma unroll
    for (int it = 0; it < 8; it++) {
        int idx = t + it * 256;
        int row = idx >> 4;
        int c4  = (idx & 15) << 2;
        *(uint4*)&Qs[row][c4] = *(const uint4*)&qp[row * DI + c4];
    }

    // cp.async K/V tile copy into buffer
    auto cp_tile = [&](int jt, int buf) {
        const float* kp = g_k + ((size_t)b * SEQ + jt * 64) * DI;
        const float* vp = g_v + ((size_t)b * SEQ + jt * 64) * DI;
        uint32_t kb = sb + (OFF_K + buf * 64*KST) * 4;
        uint32_t vb = sb + (OFF_V + buf * 64*VST) * 4;
        #pragma unroll
        for (int it = 0; it < 4; it++) {
            int idx = t + it * 256;
            int row = idx >> 4;
            int c4  = (idx & 15) << 2;
            cpa16(kb + (row * KST + c4) * 4, kp + row * DI + c4);
            cpa16(vb + (row * VST + c4) * 4, vp + row * DI + c4);
        }
        cpa_commit();
    };

    cp_tile(jt0, 0);

    float m0r = -1e30f, m1r = -1e30f, l0r = 0.f, l1r = 0.f;
    float o[8][4];
    #pragma unroll
    for (int n = 0; n < 8; n++)
        #pragma unroll
        for (int j = 0; j < 4; j++) o[n][j] = 0.f;

    for (int jt = jt0; jt < jt1; jt++) {
        const int buf = (jt - jt0) & 1;
        const uint32_t* Ks = smu + OFF_K + buf * 64*KST;   // [j][d] stride 68
        const uint32_t* Vs = smu + OFF_V + buf * 64*VST;   // [j][e] stride 72

        if (jt + 1 < jt1) { cp_tile(jt + 1, buf ^ 1); cpa_wait<1>(); }
        else              { cpa_wait<0>(); }
        __syncthreads();

        // S = Q K^T
        float sv[8][4];
        #pragma unroll
        for (int n = 0; n < 8; n++)
            #pragma unroll
            for (int j = 0; j < 4; j++) sv[n][j] = 0.f;

        #pragma unroll
        for (int kk = 0; kk < 64; kk += 8) {
            uint32_t a0 = Qs[m0+g][kk+tig];
            uint32_t a1 = Qs[m0+g+8][kk+tig];
            uint32_t a2 = Qs[m0+g][kk+tig+4];
            uint32_t a3 = Qs[m0+g+8][kk+tig+4];
            #pragma unroll
            for (int n = 0; n < 8; n++) {
                uint32_t b0 = Ks[(n*8+g) * KST + kk+tig];
                uint32_t b1 = Ks[(n*8+g) * KST + kk+tig+4];
                mma_tf32(sv[n], a0, a1, a2, a3, b0, b1);
            }
        }

        const int row0 = q0 + m0 + g;
        const int row1 = row0 + 8;
        if (jt >= 2*qt) {  // diagonal tiles
            #pragma unroll
            for (int n = 0; n < 8; n++) {
                int col = jt*64 + n*8 + tig*2;
                if (col     > row0) sv[n][0] = -1e30f;
                if (col + 1 > row0) sv[n][1] = -1e30f;
                if (col     > row1) sv[n][2] = -1e30f;
                if (col + 1 > row1) sv[n][3] = -1e30f;
            }
        }

        // Online softmax (2 rows/lane, quad reduce)
        float mx0 = -1e30f, mx1 = -1e30f;
        #pragma unroll
        for (int n = 0; n < 8; n++) {
            mx0 = fmaxf(mx0, fmaxf(sv[n][0], sv[n][1]));
            mx1 = fmaxf(mx1, fmaxf(sv[n][2], sv[n][3]));
        }
        mx0 = fmaxf(mx0, __shfl_xor_sync(0xffffffffu, mx0, 1));
        mx0 = fmaxf(mx0, __shfl_xor_sync(0xffffffffu, mx0, 2));
        mx1 = fmaxf(mx1, __shfl_xor_sync(0xffffffffu, mx1, 1));
        mx1 = fmaxf(mx1, __shfl_xor_sync(0xffffffffu, mx1, 2));

        float nm0 = fmaxf(m0r, mx0), nm1 = fmaxf(m1r, mx1);
        float sc0 = __expf(m0r - nm0), sc1 = __expf(m1r - nm1);
        float rs0 = 0.f, rs1 = 0.f;
        uint32_t pv[8][4];
        #pragma unroll
        for (int n = 0; n < 8; n++) {
            float p00 = __expf(sv[n][0] - nm0);
            float p01 = __expf(sv[n][1] - nm0);
            float p10 = __expf(sv[n][2] - nm1);
            float p11 = __expf(sv[n][3] - nm1);
            rs0 += p00 + p01;
            rs1 += p10 + p11;
            pv[n][0] = f2tf32(p00); pv[n][1] = f2tf32(p01);
            pv[n][2] = f2tf32(p10); pv[n][3] = f2tf32(p11);
            o[n][0] *= sc0; o[n][1] *= sc0;
            o[n][2] *= sc1; o[n][3] *= sc1;
        }
        rs0 += __shfl_xor_sync(0xffffffffu, rs0, 1);
        rs0 += __shfl_xor_sync(0xffffffffu, rs0, 2);
        rs1 += __shfl_xor_sync(0xffffffffu, rs1, 1);
        rs1 += __shfl_xor_sync(0xffffffffu, rs1, 2);
        l0r = l0r * sc0 + rs0; m0r = nm0;
        l1r = l1r * sc1 + rs1; m1r = nm1;

        // O += P V: build P A-fragments from S fragment via shfl.
        // Col c of rows (g, g+8) lives on lane 4g + (c>>1), element c&1.
        const int Lsrc = (lane & ~3) | (tig >> 1);
        #pragma unroll
        for (int n = 0; n < 8; n++) {     // k-group kk = n*8
            uint32_t s00 = __shfl_sync(0xffffffffu, pv[n][0], Lsrc);
            uint32_t s01 = __shfl_sync(0xffffffffu, pv[n][1], Lsrc);
            uint32_t s10 = __shfl_sync(0xffffffffu, pv[n][2], Lsrc);
            uint32_t s11 = __shfl_sync(0xffffffffu, pv[n][3], Lsrc);
            uint32_t t00 = __shfl_sync(0xffffffffu, pv[n][0], Lsrc + 2);
            uint32_t t01 = __shfl_sync(0xffffffffu, pv[n][1], Lsrc + 2);
            uint32_t t10 = __shfl_sync(0xffffffffu, pv[n][2], Lsrc + 2);
            uint32_t t11 = __shfl_sync(0xffffffffu, pv[n][3], Lsrc + 2);
            uint32_t a0 = (tig & 1) ? s01 : s00;   // row g,   col kk+tig
            uint32_t a1 = (tig & 1) ? s11 : s10;   // row g+8, col kk+tig
            uint32_t a2 = (tig & 1) ? t01 : t00;   // row g,   col kk+tig+4
            uint32_t a3 = (tig & 1) ? t11 : t10;   // row g+8, col kk+tig+4
            const int kk = n * 8;
            #pragma unroll
            for (int n2 = 0; n2 < 8; n2++) {
                uint32_t b0 = Vs[(kk+tig)   * VST + n2*8 + g];
                uint32_t b1 = Vs[(kk+tig+4) * VST + n2*8 + g];
                mma_tf32(o[n2], a0, a1, a2, a3, b0, b1);
            }
        }
        __syncthreads();   // all warps done with buf before it is refilled
    }

    // Emit unnormalized partial + stats
    const int unit = ((b * 16 + qt) << 2) + s;
    float* Od = g_opart + (size_t)unit * 128 * 64;
    if (tig == 0) {
        g_mpart[unit*128 + m0 + g]     = m0r;
        g_lpart[unit*128 + m0 + g]     = l0r;
        g_mpart[unit*128 + m0 + g + 8] = m1r;
        g_lpart[unit*128 + m0 + g + 8] = l1r;
    }
    #pragma unroll
    for (int n = 0; n < 8; n++) {
        int col = n*8 + tig*2;
        *(float2*)&Od[(m0 + g) * 64 + col]     = make_float2(o[n][0], o[n][1]);
        *(float2*)&Od[(m0 + g + 8) * 64 + col] = make_float2(o[n][2], o[n][3]);
    }
}

// ---------------------------------------------------------------------------
// Combine partials + normalize + fused output projection.
// One block per (b, qt, half64) = 256 blocks, 128 threads.
// ---------------------------------------------------------------------------
#define TSTR 68

__global__ __launch_bounds__(128)
void combine_kernel(const float* __restrict__ W0, const float* __restrict__ b0,
                    float* __restrict__ out)
{
    __shared__ float scale_s[4][64];
    __shared__ float invl_s[64];
    __shared__ float Ot[64][TSTR];
    __shared__ float Ws[64][TSTR];

    const int t    = threadIdx.x;
    const int tx   = t & 15;
    const int ty   = t >> 4;
    const int b    = blockIdx.x >> 5;
    const int qh   = blockIdx.x & 31;
    const int qt   = qh >> 1;
    const int half = qh & 1;
    const int ro   = half * 64;
    const int ns   = ((2*qt + 1) >> 3) + 1;
    const int base = (b * 16 + qt) << 2;

    if (t < 64) {
        float ms[4];
        float mm = -1e30f;
        for (int s = 0; s < ns; s++) {
            ms[s] = g_mpart[(base + s) * 128 + ro + t];
            mm = fmaxf(mm, ms[s]);
        }
        float ll = 0.f;
        for (int s = 0; s < ns; s++) {
            float sc = __expf(ms[s] - mm);
            scale_s[s][t] = sc;
            ll += g_lpart[(base + s) * 128 + ro + t] * sc;
        }
        invl_s[t] = 1.0f / ll;
    }
    #pragma unroll
    for (int it = 0; it < 8; it++) {
        int idx = t + it * 128;
        int row = idx >> 4;
        int c   = (idx & 15) << 2;
        *(float4*)&Ws[row][c] = *(const float4*)&W0[row * 64 + c];
    }
    __syncthreads();

    #pragma unroll
    for (int i = 0; i < 8; i++) {
        int row = ty * 8 + i;
        float4 v = make_float4(0.f, 0.f, 0.f, 0.f);
        for (int s = 0; s < ns; s++) {
            const float* Op = g_opart + (size_t)(base + s) * 8192;
            float4 o4 = *(const float4*)&Op[(ro + row) * 64 + tx*4];
            float sc = scale_s[s][row];
            v.x = fmaf(o4.x, sc, v.x); v.y = fmaf(o4.y, sc, v.y);
            v.z = fmaf(o4.z, sc, v.z); v.w = fmaf(o4.w, sc, v.w);
        }
        float inv = invl_s[row];
        Ot[tx*4 + 0][row] = v.x * inv;
        Ot[tx*4 + 1][row] = v.y * inv;
        Ot[tx*4 + 2][row] = v.z * inv;
        Ot[tx*4 + 3][row] = v.w * inv;
    }
    __syncthreads();

    float res[8][4];
    #pragma unroll
    for (int i = 0; i < 8; i++)
        #pragma unroll
        for (int j = 0; j < 4; j++) res[i][j] = 0.f;

    #pragma unroll 8
    for (int e = 0; e < 64; e++) {
        float4 a0 = *(const float4*)&Ot[e][ty*8];
        float4 a1 = *(const float4*)&Ot[e][ty*8 + 4];
        float4 w4 = *(const float4*)&Ws[e][tx*4];
        float av[8] = {a0.x,a0.y,a0.z,a0.w,a1.x,a1.y,a1.z,a1.w};
        float wv[4] = {w4.x,w4.y,w4.z,w4.w};
        #pragma unroll
        for (int i = 0; i < 8; i++)
            #pragma unroll
            for (int o2 = 0; o2 < 4; o2++)
                res[i][o2] = fmaf(av[i], wv[o2], res[i][o2]);
    }

    float4 bb = *(const float4*)&b0[tx*4];
    float bv4[4] = {bb.x, bb.y, bb.z, bb.w};
    #pragma unroll
    for (int i = 0; i < 8; i++) {
        float4 o4;
        o4.x = res[i][0] + bv4[0];
        o4.y = res[i][1] + bv4[1];
        o4.z = res[i][2] + bv4[2];
        o4.w = res[i][3] + bv4[3];
        *(float4*)&out[((size_t)b * SEQ + qt*128 + ro + ty*8 + i) * DI + tx*4] = o4;
    }
}

// ---------------------------------------------------------------------------
extern "C" void kernel_launch(void* const* d_in, const int* in_sizes, int n_in,
                              void* d_out, int out_size)
{
    const float* X  = (const float*)d_in[0];
    const float* Wk = (const float*)d_in[1];
    const float* bk = (const float*)d_in[2];
    const float* Wq = (const float*)d_in[3];
    const float* bq = (const float*)d_in[4];
    const float* Wv = (const float*)d_in[5];
    const float* bv = (const float*)d_in[6];
    const float* W0 = (const float*)d_in[7];
    const float* b0 = (const float*)d_in[8];
    float* out = (float*)d_out;

    const int attn_smem = (128*QST + 2*64*KST + 2*64*VST) * (int)sizeof(uint32_t); // 106496
    cudaFuncSetAttribute(attn_part_kernel, cudaFuncAttributeMaxDynamicSharedMemorySize,
                         attn_smem);

    dim3 pg(NB * SEQ / 128, 3);
    proj_kernel<<<pg, 256>>>(X, Wq, bq, Wk, bk, Wv, bv);
    attn_part_kernel<<<NB * 40, 256, attn_smem>>>();
    combine_kernel<<<NB * 32, 128>>>(W0, b0, out);
}

// round 9
// speedup vs baseline: 3.4466x; 1.0085x over previous
#include <cuda_runtime.h>
#include <cstdint>

#define SEQ 2048
#define DM  1024
#define DI  64
#define NB  8

__device__ float g_q[NB*SEQ*DI];   // stored pre-rounded to tf32, Q pre-scaled by 1/8
__device__ float g_k[NB*SEQ*DI];
__device__ float g_v[NB*SEQ*DI];

// Split partials: q-tile=128 rows, up to 4 splits. unit = (b*16+qt)*4+s
__device__ float g_opart[NB*16*4*128*64];
__device__ float g_mpart[NB*16*4*128];
__device__ float g_lpart[NB*16*4*128];

__device__ __forceinline__ uint32_t f2tf32(float x) {
    uint32_t r;
    asm("cvt.rna.tf32.f32 %0, %1;" : "=r"(r) : "f"(x));
    return r;
}
__device__ __forceinline__ float rnd_tf32(float x) {
    return __uint_as_float(f2tf32(x));
}

__device__ __forceinline__ void mma_tf32(float c[4],
    uint32_t a0, uint32_t a1, uint32_t a2, uint32_t a3,
    uint32_t b0, uint32_t b1)
{
    asm volatile(
        "mma.sync.aligned.m16n8k8.row.col.f32.tf32.tf32.f32 "
        "{%0,%1,%2,%3}, {%4,%5,%6,%7}, {%8,%9}, {%0,%1,%2,%3};"
        : "+f"(c[0]), "+f"(c[1]), "+f"(c[2]), "+f"(c[3])
        : "r"(a0), "r"(a1), "r"(a2), "r"(a3), "r"(b0), "r"(b1));
}

__device__ __forceinline__ void cpa16(uint32_t dst, const void* src) {
    asm volatile("cp.async.ca.shared.global [%0], [%1], 16;" :: "r"(dst), "l"(src));
}
__device__ __forceinline__ void cpa_commit() {
    asm volatile("cp.async.commit_group;");
}
template<int N> __device__ __forceinline__ void cpa_wait() {
    asm volatile("cp.async.wait_group %0;" :: "n"(N));
}

// ---------------------------------------------------------------------------
// QKV projection: 256 threads (8 warps: 4 row-groups x 2 col-groups),
// block tile 128x64, warp tile m32 x n32, K-chunk 32.
// DOUBLE-BUFFERED smem: one __syncthreads per chunk; cvt+store of chunk c+1
// and LDG of chunk c+2 overlap the mma of chunk c.
// A smem [row][k] stride 36 (reads bank 4g+tig: conflict-free)
// B smem [k][n]   stride 72 (reads bank 8tig+8n+g: conflict-free)
// ---------------------------------------------------------------------------
__global__ __launch_bounds__(256)
void proj_kernel(const float* __restrict__ X,
                 const float* __restrict__ Wq, const float* __restrict__ bq,
                 const float* __restrict__ Wk, const float* __restrict__ bk,
                 const float* __restrict__ Wv, const float* __restrict__ bv)
{
    __shared__ uint32_t As[2][128][36];
    __shared__ uint32_t Bs[2][32][72];

    const float* W; const float* bi; float* dst; float scale = 1.0f;
    if (blockIdx.y == 0)      { W = Wq; bi = bq; dst = g_q; scale = 0.125f; }
    else if (blockIdx.y == 1) { W = Wk; bi = bk; dst = g_k; }
    else                      { W = Wv; bi = bv; dst = g_v; }

    const int t    = threadIdx.x;
    const int w    = t >> 5;
    const int wr   = w & 3;        // row group: m32
    const int wc   = w >> 2;       // col group: n32
    const int lane = t & 31;
    const int g    = lane >> 2;
    const int tig  = lane & 3;
    const int m0   = wr * 32;
    const int n0   = wc * 32;
    const size_t r0 = (size_t)blockIdx.x * 128;

    // per-thread gmem source coordinates (fixed across chunks)
    const int arow = t >> 1;               // 4 iters of 256 -> rows via idx>>3
    const int ac0  = (t & 1) << 4;         // unused pattern replaced below

    float4 ra[4], rb[2];

    auto load_regs = [&](int kb) {
        #pragma unroll
        for (int it = 0; it < 4; it++) {
            int idx = t + it * 256;
            ra[it] = *(const float4*)&X[(r0 + (idx >> 3)) * DM + kb + ((idx & 7) << 2)];
        }
        #pragma unroll
        for (int it = 0; it < 2; it++) {
            int idx = t + it * 256;
            rb[it] = *(const float4*)&W[(size_t)(kb + (idx >> 4)) * DI + ((idx & 15) << 2)];
        }
    };
    auto store_buf = [&](int p) {
        #pragma unroll
        for (int it = 0; it < 4; it++) {
            int idx = t + it * 256;
            *(uint4*)&As[p][idx >> 3][(idx & 7) << 2] =
                make_uint4(f2tf32(ra[it].x), f2tf32(ra[it].y),
                           f2tf32(ra[it].z), f2tf32(ra[it].w));
        }
        #pragma unroll
        for (int it = 0; it < 2; it++) {
            int idx = t + it * 256;
            *(uint4*)&Bs[p][idx >> 4][(idx & 15) << 2] =
                make_uint4(f2tf32(rb[it].x), f2tf32(rb[it].y),
                           f2tf32(rb[it].z), f2tf32(rb[it].w));
        }
    };

    float c[2][4][4];
    #pragma unroll
    for (int mt = 0; mt < 2; mt++)
        #pragma unroll
        for (int n = 0; n < 4; n++)
            #pragma unroll
            for (int j = 0; j < 4; j++) c[mt][n][j] = 0.f;

    // Prologue: chunk 0 -> buf 0; prefetch chunk 1 into regs
    load_regs(0);
    store_buf(0);
    load_regs(32);

    #pragma unroll 1
    for (int ci = 0; ci < 32; ci++) {
        const int p = ci & 1;
        __syncthreads();   // chunk ci stores visible; buf p^1 reads (chunk ci-1) done
        if (ci + 1 < 32) {
            store_buf(p ^ 1);                       // chunk ci+1 regs -> other buffer
            if (ci + 2 < 32) load_regs((ci + 2) * 32);  // prefetch chunk ci+2
        }
        #pragma unroll
        for (int kk = 0; kk < 32; kk += 8) {
            uint32_t a[2][4];
            #pragma unroll
            for (int mt = 0; mt < 2; mt++) {
                int r = m0 + mt * 16 + g;
                a[mt][0] = As[p][r][kk + tig];
                a[mt][1] = As[p][r + 8][kk + tig];
                a[mt][2] = As[p][r][kk + tig + 4];
                a[mt][3] = As[p][r + 8][kk + tig + 4];
            }
            #pragma unroll
            for (int n = 0; n < 4; n++) {
                uint32_t b0 = Bs[p][kk + tig][n0 + n*8 + g];
                uint32_t b1 = Bs[p][kk + tig + 4][n0 + n*8 + g];
                mma_tf32(c[0][n], a[0][0], a[0][1], a[0][2], a[0][3], b0, b1);
                mma_tf32(c[1][n], a[1][0], a[1][1], a[1][2], a[1][3], b0, b1);
            }
        }
    }

    #pragma unroll
    for (int mt = 0; mt < 2; mt++)
        #pragma unroll
        for (int n = 0; n < 4; n++) {
            int col = n0 + n*8 + tig*2;
            float bv0 = bi[col], bv1 = bi[col+1];
            size_t rr = r0 + m0 + mt*16 + g;
            *(float2*)&dst[rr * DI + col] =
                make_float2(rnd_tf32((c[mt][n][0] + bv0) * scale),
                            rnd_tf32((c[mt][n][1] + bv1) * scale));
            *(float2*)&dst[(rr + 8) * DI + col] =
                make_float2(rnd_tf32((c[mt][n][2] + bv0) * scale),
                            rnd_tf32((c[mt][n][3] + bv1) * scale));
        }
}

// ---------------------------------------------------------------------------
// Split-KV flash attention. q-tile 128 (8 warps x m16), kv tile 64,
// chunk = 8 kv tiles => 40 units/batch, 320 blocks x 256 threads.
// K/V double-buffered via cp.async; P A-fragments via shfl (no smem trip).
// ---------------------------------------------------------------------------
#define QST 68
#define KST 68
#define VST 72
#define OFF_K 8704
#define OFF_V 17408

__global__ __launch_bounds__(256)
void attn_part_kernel()
{
    extern __shared__ uint32_t smu[];
    uint32_t (*Qs)[QST] = (uint32_t(*)[QST])(smu);
    const uint32_t sb = (uint32_t)__cvta_generic_to_shared(smu);

    const int t    = threadIdx.x;
    const int lane = t & 31;
    const int g    = lane >> 2;
    const int tig  = lane & 3;
    const int m0   = (t >> 5) * 16;

    // Decode (b, qt, s): 40 units per batch, qt in [0,16), chunk = 8 kv tiles
    const int b = blockIdx.x / 40;
    int u = blockIdx.x % 40;
    int qt = 0, s = 0;
    #pragma unroll 1
    for (qt = 0; qt < 16; qt++) {
        int ns = ((2*qt + 1) >> 3) + 1;
        if (u < ns) { s = u; break; }
        u -= ns;
    }
    const int q0  = qt * 128;
    const int jt0 = s * 8;
    const int jt1 = min(jt0 + 8, 2*qt + 2);

    // Load Q tile (pre-rounded tf32, pre-scaled): raw bit copy
    const float* qp = g_q + ((size_t)b * SEQ + q0) * DI;
    #pragma unroll
    for (int it = 0; it < 8; it++) {
        int idx = t + it * 256;
        int row = idx >> 4;
        int c4  = (idx & 15) << 2;
        *(uint4*)&Qs[row][c4] = *(const uint4*)&qp[row * DI + c4];
    }

    auto cp_tile = [&](int jt, int buf) {
        const float* kp = g_k + ((size_t)b * SEQ + jt * 64) * DI;
        const float* vp = g_v + ((size_t)b * SEQ + jt * 64) * DI;
        uint32_t kb = sb + (OFF_K + buf * 64*KST) * 4;
        uint32_t vb = sb + (OFF_V + buf * 64*VST) * 4;
        #pragma unroll
        for (int it = 0; it < 4; it++) {
            int idx = t + it * 256;
            int row = idx >> 4;
            int c4  = (idx & 15) << 2;
            cpa16(kb + (row * KST + c4) * 4, kp + row * DI + c4);
            cpa16(vb + (row * VST + c4) * 4, vp + row * DI + c4);
        }
        cpa_commit();
    };

    cp_tile(jt0, 0);

    float m0r = -1e30f, m1r = -1e30f, l0r = 0.f, l1r = 0.f;
    float o[8][4];
    #pragma unroll
    for (int n = 0; n < 8; n++)
        #pragma unroll
        for (int j = 0; j < 4; j++) o[n][j] = 0.f;

    for (int jt = jt0; jt < jt1; jt++) {
        const int buf = (jt - jt0) & 1;
        const uint32_t* Ks = smu + OFF_K + buf * 64*KST;   // [j][d] stride 68
        const uint32_t* Vs = smu + OFF_V + buf * 64*VST;   // [j][e] stride 72

        if (jt + 1 < jt1) { cp_tile(jt + 1, buf ^ 1); cpa_wait<1>(); }
        else              { cpa_wait<0>(); }
        __syncthreads();

        // S = Q K^T
        float sv[8][4];
        #pragma unroll
        for (int n = 0; n < 8; n++)
            #pragma unroll
            for (int j = 0; j < 4; j++) sv[n][j] = 0.f;

        #pragma unroll
        for (int kk = 0; kk < 64; kk += 8) {
            uint32_t a0 = Qs[m0+g][kk+tig];
            uint32_t a1 = Qs[m0+g+8][kk+tig];
            uint32_t a2 = Qs[m0+g][kk+tig+4];
            uint32_t a3 = Qs[m0+g+8][kk+tig+4];
            #pragma unroll
            for (int n = 0; n < 8; n++) {
                uint32_t b0 = Ks[(n*8+g) * KST + kk+tig];
                uint32_t b1 = Ks[(n*8+g) * KST + kk+tig+4];
                mma_tf32(sv[n], a0, a1, a2, a3, b0, b1);
            }
        }

        const int row0 = q0 + m0 + g;
        const int row1 = row0 + 8;
        if (jt >= 2*qt) {  // diagonal tiles
            #pragma unroll
            for (int n = 0; n < 8; n++) {
                int col = jt*64 + n*8 + tig*2;
                if (col     > row0) sv[n][0] = -1e30f;
                if (col + 1 > row0) sv[n][1] = -1e30f;
                if (col     > row1) sv[n][2] = -1e30f;
                if (col + 1 > row1) sv[n][3] = -1e30f;
            }
        }

        // Online softmax (2 rows/lane, quad reduce)
        float mx0 = -1e30f, mx1 = -1e30f;
        #pragma unroll
        for (int n = 0; n < 8; n++) {
            mx0 = fmaxf(mx0, fmaxf(sv[n][0], sv[n][1]));
            mx1 = fmaxf(mx1, fmaxf(sv[n][2], sv[n][3]));
        }
        mx0 = fmaxf(mx0, __shfl_xor_sync(0xffffffffu, mx0, 1));
        mx0 = fmaxf(mx0, __shfl_xor_sync(0xffffffffu, mx0, 2));
        mx1 = fmaxf(mx1, __shfl_xor_sync(0xffffffffu, mx1, 1));
        mx1 = fmaxf(mx1, __shfl_xor_sync(0xffffffffu, mx1, 2));

        float nm0 = fmaxf(m0r, mx0), nm1 = fmaxf(m1r, mx1);
        float sc0 = __expf(m0r - nm0), sc1 = __expf(m1r - nm1);
        float rs0 = 0.f, rs1 = 0.f;
        uint32_t pv[8][4];
        #pragma unroll
        for (int n = 0; n < 8; n++) {
            float p00 = __expf(sv[n][0] - nm0);
            float p01 = __expf(sv[n][1] - nm0);
            float p10 = __expf(sv[n][2] - nm1);
            float p11 = __expf(sv[n][3] - nm1);
            rs0 += p00 + p01;
            rs1 += p10 + p11;
            pv[n][0] = f2tf32(p00); pv[n][1] = f2tf32(p01);
            pv[n][2] = f2tf32(p10); pv[n][3] = f2tf32(p11);
            o[n][0] *= sc0; o[n][1] *= sc0;
            o[n][2] *= sc1; o[n][3] *= sc1;
        }
        rs0 += __shfl_xor_sync(0xffffffffu, rs0, 1);
        rs0 += __shfl_xor_sync(0xffffffffu, rs0, 2);
        rs1 += __shfl_xor_sync(0xffffffffu, rs1, 1);
        rs1 += __shfl_xor_sync(0xffffffffu, rs1, 2);
        l0r = l0r * sc0 + rs0; m0r = nm0;
        l1r = l1r * sc1 + rs1; m1r = nm1;

        // O += P V: P A-fragments via shfl column exchange.
        const int Lsrc = (lane & ~3) | (tig >> 1);
        #pragma unroll
        for (int n = 0; n < 8; n++) {     // k-group kk = n*8
            uint32_t s00 = __shfl_sync(0xffffffffu, pv[n][0], Lsrc);
            uint32_t s01 = __shfl_sync(0xffffffffu, pv[n][1], Lsrc);
            uint32_t s10 = __shfl_sync(0xffffffffu, pv[n][2], Lsrc);
            uint32_t s11 = __shfl_sync(0xffffffffu, pv[n][3], Lsrc);
            uint32_t t00 = __shfl_sync(0xffffffffu, pv[n][0], Lsrc + 2);
            uint32_t t01 = __shfl_sync(0xffffffffu, pv[n][1], Lsrc + 2);
            uint32_t t10 = __shfl_sync(0xffffffffu, pv[n][2], Lsrc + 2);
            uint32_t t11 = __shfl_sync(0xffffffffu, pv[n][3], Lsrc + 2);
            uint32_t a0 = (tig & 1) ? s01 : s00;
            uint32_t a1 = (tig & 1) ? s11 : s10;
            uint32_t a2 = (tig & 1) ? t01 : t00;
            uint32_t a3 = (tig & 1) ? t11 : t10;
            const int kk = n * 8;
            #pragma unroll
            for (int n2 = 0; n2 < 8; n2++) {
                uint32_t b0 = Vs[(kk+tig)   * VST + n2*8 + g];
                uint32_t b1 = Vs[(kk+tig+4) * VST + n2*8 + g];
                mma_tf32(o[n2], a0, a1, a2, a3, b0, b1);
            }
        }
        __syncthreads();   // all warps done with buf before refill
    }

    // Emit unnormalized partial + stats
    const int unit = ((b * 16 + qt) << 2) + s;
    float* Od = g_opart + (size_t)unit * 128 * 64;
    if (tig == 0) {
        g_mpart[unit*128 + m0 + g]     = m0r;
        g_lpart[unit*128 + m0 + g]     = l0r;
        g_mpart[unit*128 + m0 + g + 8] = m1r;
        g_lpart[unit*128 + m0 + g + 8] = l1r;
    }
    #pragma unroll
    for (int n = 0; n < 8; n++) {
        int col = n*8 + tig*2;
        *(float2*)&Od[(m0 + g) * 64 + col]     = make_float2(o[n][0], o[n][1]);
        *(float2*)&Od[(m0 + g + 8) * 64 + col] = make_float2(o[n][2], o[n][3]);
    }
}

// ---------------------------------------------------------------------------
// Combine partials + normalize + fused output projection.
// One block per (b, qt, half64) = 256 blocks, 128 threads.
// ---------------------------------------------------------------------------
#define TSTR 68

__global__ __launch_bounds__(128)
void combine_kernel(const float* __restrict__ W0, const float* __restrict__ b0,
                    float* __restrict__ out)
{
    __shared__ float scale_s[4][64];
    __shared__ float invl_s[64];
    __shared__ float Ot[64][TSTR];
    __shared__ float Ws[64][TSTR];

    const int t    = threadIdx.x;
    const int tx   = t & 15;
    const int ty   = t >> 4;
    const int b    = blockIdx.x >> 5;
    const int qh   = blockIdx.x & 31;
    const int qt   = qh >> 1;
    const int half = qh & 1;
    const int ro   = half * 64;
    const int ns   = ((2*qt + 1) >> 3) + 1;
    const int base = (b * 16 + qt) << 2;

    if (t < 64) {
        float ms[4];
        float mm = -1e30f;
        for (int s = 0; s < ns; s++) {
            ms[s] = g_mpart[(base + s) * 128 + ro + t];
            mm = fmaxf(mm, ms[s]);
        }
        float ll = 0.f;
        for (int s = 0; s < ns; s++) {
            float sc = __expf(ms[s] - mm);
            scale_s[s][t] = sc;
            ll += g_lpart[(base + s) * 128 + ro + t] * sc;
        }
        invl_s[t] = 1.0f / ll;
    }
    #pragma unroll
    for (int it = 0; it < 8; it++) {
        int idx = t + it * 128;
        int row = idx >> 4;
        int c   = (idx & 15) << 2;
        *(float4*)&Ws[row][c] = *(const float4*)&W0[row * 64 + c];
    }
    __syncthreads();

    #pragma unroll
    for (int i = 0; i < 8; i++) {
        int row = ty * 8 + i;
        float4 v = make_float4(0.f, 0.f, 0.f, 0.f);
        for (int s = 0; s < ns; s++) {
            const float* Op = g_opart + (size_t)(base + s) * 8192;
            float4 o4 = *(const float4*)&Op[(ro + row) * 64 + tx*4];
            float sc = scale_s[s][row];
            v.x = fmaf(o4.x, sc, v.x); v.y = fmaf(o4.y, sc, v.y);
            v.z = fmaf(o4.z, sc, v.z); v.w = fmaf(o4.w, sc, v.w);
        }
        float inv = invl_s[row];
        Ot[tx*4 + 0][row] = v.x * inv;
        Ot[tx*4 + 1][row] = v.y * inv;
        Ot[tx*4 + 2][row] = v.z * inv;
        Ot[tx*4 + 3][row] = v.w * inv;
    }
    __syncthreads();

    float res[8][4];
    #pragma unroll
    for (int i = 0; i < 8; i++)
        #pragma unroll
        for (int j = 0; j < 4; j++) res[i][j] = 0.f;

    #pragma unroll 8
    for (int e = 0; e < 64; e++) {
        float4 a0 = *(const float4*)&Ot[e][ty*8];
        float4 a1 = *(const float4*)&Ot[e][ty*8 + 4];
        float4 w4 = *(const float4*)&Ws[e][tx*4];
        float av[8] = {a0.x,a0.y,a0.z,a0.w,a1.x,a1.y,a1.z,a1.w};
        float wv[4] = {w4.x,w4.y,w4.z,w4.w};
        #pragma unroll
        for (int i = 0; i < 8; i++)
            #pragma unroll
            for (int o2 = 0; o2 < 4; o2++)
                res[i][o2] = fmaf(av[i], wv[o2], res[i][o2]);
    }

    float4 bb = *(const float4*)&b0[tx*4];
    float bv4[4] = {bb.x, bb.y, bb.z, bb.w};
    #pragma unroll
    for (int i = 0; i < 8; i++) {
        float4 o4;
        o4.x = res[i][0] + bv4[0];
        o4.y = res[i][1] + bv4[1];
        o4.z = res[i][2] + bv4[2];
        o4.w = res[i][3] + bv4[3];
        *(float4*)&out[((size_t)b * SEQ + qt*128 + ro + ty*8 + i) * DI + tx*4] = o4;
    }
}

// ---------------------------------------------------------------------------
extern "C" void kernel_launch(void* const* d_in, const int* in_sizes, int n_in,
                              void* d_out, int out_size)
{
    const float* X  = (const float*)d_in[0];
    const float* Wk = (const float*)d_in[1];
    const float* bk = (const float*)d_in[2];
    const float* Wq = (const float*)d_in[3];
    const float* bq = (const float*)d_in[4];
    const float* Wv = (const float*)d_in[5];
    const float* bv = (const float*)d_in[6];
    const float* W0 = (const float*)d_in[7];
    const float* b0 = (const float*)d_in[8];
    float* out = (float*)d_out;

    const int attn_smem = (128*QST + 2*64*KST + 2*64*VST) * (int)sizeof(uint32_t); // 106496
    cudaFuncSetAttribute(attn_part_kernel, cudaFuncAttributeMaxDynamicSharedMemorySize,
                         attn_smem);

    dim3 pg(NB * SEQ / 128, 3);
    proj_kernel<<<pg, 256>>>(X, Wq, bq, Wk, bk, Wv, bv);
    attn_part_kernel<<<NB * 40, 256, attn_smem>>>();
    combine_kernel<<<NB * 32, 128>>>(W0, b0, out);
}

// round 10
// speedup vs baseline: 3.5569x; 1.0320x over previous
#include <cuda_runtime.h>
#include <cstdint>

#define SEQ 2048
#define DM  1024
#define DI  64
#define NB  8

__device__ float g_q[NB*SEQ*DI];   // tf32-rounded, Q pre-scaled by 1/8
__device__ float g_k[NB*SEQ*DI];
__device__ float g_v[NB*SEQ*DI];

__device__ uint32_t g_wb[DM*192];  // fused [Wq/8 | Wk | Wv] as tf32 bits, k-major
__device__ float    g_bb[192];     // fused [bq/8 | bk | bv]

// Split partials: q-tile=128 rows, up to 4 splits. unit = (b*16+qt)*4+s
__device__ float g_opart[NB*16*4*128*64];
__device__ float g_mpart[NB*16*4*128];
__device__ float g_lpart[NB*16*4*128];

__device__ __forceinline__ uint32_t f2tf32(float x) {
    uint32_t r;
    asm("cvt.rna.tf32.f32 %0, %1;" : "=r"(r) : "f"(x));
    return r;
}
__device__ __forceinline__ float rnd_tf32(float x) {
    return __uint_as_float(f2tf32(x));
}

__device__ __forceinline__ void mma_tf32(float c[4],
    uint32_t a0, uint32_t a1, uint32_t a2, uint32_t a3,
    uint32_t b0, uint32_t b1)
{
    asm volatile(
        "mma.sync.aligned.m16n8k8.row.col.f32.tf32.tf32.f32 "
        "{%0,%1,%2,%3}, {%4,%5,%6,%7}, {%8,%9}, {%0,%1,%2,%3};"
        : "+f"(c[0]), "+f"(c[1]), "+f"(c[2]), "+f"(c[3])
        : "r"(a0), "r"(a1), "r"(a2), "r"(a3), "r"(b0), "r"(b1));
}

__device__ __forceinline__ void cpa16(uint32_t dst, const void* src) {
    asm volatile("cp.async.ca.shared.global [%0], [%1], 16;" :: "r"(dst), "l"(src));
}
__device__ __forceinline__ void cpa_commit() {
    asm volatile("cp.async.commit_group;");
}
template<int N> __device__ __forceinline__ void cpa_wait() {
    asm volatile("cp.async.wait_group %0;" :: "n"(N));
}

// ---------------------------------------------------------------------------
// Prep: fuse + tf32-round the three weight matrices (Wq pre-scaled by 1/8).
// ---------------------------------------------------------------------------
__global__ void prep_kernel(const float* __restrict__ Wq, const float* __restrict__ bq,
                            const float* __restrict__ Wk, const float* __restrict__ bk,
                            const float* __restrict__ Wv, const float* __restrict__ bv)
{
    int i = blockIdx.x * 256 + threadIdx.x;
    if (i < DM * 192) {
        int k = i / 192, n = i % 192;
        const float* W = (n < 64) ? Wq : (n < 128) ? Wk : Wv;
        float v = W[k * 64 + (n & 63)];
        if (n < 64) v *= 0.125f;
        g_wb[i] = f2tf32(v);
    }
    if (i < 192) {
        const float* B = (i < 64) ? bq : (i < 128) ? bk : bv;
        float v = B[i & 63];
        if (i < 64) v *= 0.125f;
        g_bb[i] = v;
    }
}

// ---------------------------------------------------------------------------
// Fused QKV projection: C[16384 x 192] = X[16384 x 1024] * g_wb + g_bb.
// 256 blocks x 256 threads. Block tile 64 rows x 192 cols; 8 warps =
// 2 row-groups (m32) x 4 col-groups (n48). K-chunk 16, both operands
// double-buffered: A reg-staged + cvt (4/thread/chunk), B via cp.async
// (pre-converted). One __syncthreads per chunk.
// As [row][k] stride 20 (frag reads conflict-free), Bs [k][n] stride 200
// (frag reads bank 8tig+g: conflict-free; cp.async rows contiguous).
// ---------------------------------------------------------------------------
#define NCH 64

__global__ __launch_bounds__(256, 2)
void proj_kernel(const float* __restrict__ X)
{
    __shared__ uint32_t As[2][64][20];
    __shared__ uint32_t Bs[2][16][200];

    const int t    = threadIdx.x;
    const int w    = t >> 5;
    const int wr   = w & 1;       // row group: m32
    const int wc   = w >> 1;      // col group: n48
    const int lane = t & 31;
    const int g    = lane >> 2;
    const int tig  = lane & 3;
    const int m0   = wr * 32;
    const int n0   = wc * 48;
    const size_t r0 = (size_t)blockIdx.x * 64;

    // A source: 64 rows x 16 k = 1 float4/thread
    const int arow = t >> 2;
    const int akc  = (t & 3) << 2;
    const float* aptr = X + (r0 + arow) * DM + akc;

    // B source: 16 k x 192 n = 3 cp16/thread
    int bkr[3], bc4[3];
    #pragma unroll
    for (int it = 0; it < 3; it++) {
        int idx = t + it * 256;
        bkr[it] = idx / 48;
        bc4[it] = (idx % 48) << 2;
    }

    float4 ra;
    auto loadA = [&](int kb) { ra = *(const float4*)(aptr + kb); };
    auto storeA = [&](int p) {
        *(uint4*)&As[p][arow][akc] =
            make_uint4(f2tf32(ra.x), f2tf32(ra.y), f2tf32(ra.z), f2tf32(ra.w));
    };
    auto cpB = [&](int ci, int p) {
        #pragma unroll
        for (int it = 0; it < 3; it++) {
            uint32_t d = (uint32_t)__cvta_generic_to_shared(&Bs[p][bkr[it]][bc4[it]]);
            cpa16(d, g_wb + (size_t)(ci * 16 + bkr[it]) * 192 + bc4[it]);
        }
        cpa_commit();
    };

    float c[2][6][4];
    #pragma unroll
    for (int mt = 0; mt < 2; mt++)
        #pragma unroll
        for (int n = 0; n < 6; n++)
            #pragma unroll
            for (int j = 0; j < 4; j++) c[mt][n][j] = 0.f;

    // Prologue
    loadA(0); storeA(0); cpB(0, 0);
    loadA(16);

    #pragma unroll 1
    for (int ci = 0; ci < NCH; ci++) {
        const int p = ci & 1;
        cpa_wait<0>();       // B(ci) landed
        __syncthreads();     // B(ci)/A(ci) visible; mma(ci-1) reads done
        if (ci + 1 < NCH) {
            storeA(p ^ 1);                      // A(ci+1)
            cpB(ci + 1, p ^ 1);                 // B(ci+1), overlaps mma below
            if (ci + 2 < NCH) loadA((ci + 2) * 16);
        }
        #pragma unroll
        for (int kk = 0; kk < 16; kk += 8) {
            uint32_t a[2][4];
            #pragma unroll
            for (int mt = 0; mt < 2; mt++) {
                int r = m0 + mt * 16 + g;
                a[mt][0] = As[p][r][kk + tig];
                a[mt][1] = As[p][r + 8][kk + tig];
                a[mt][2] = As[p][r][kk + tig + 4];
                a[mt][3] = As[p][r + 8][kk + tig + 4];
            }
            #pragma unroll
            for (int n = 0; n < 6; n++) {
                uint32_t b0 = Bs[p][kk + tig][n0 + n*8 + g];
                uint32_t b1 = Bs[p][kk + tig + 4][n0 + n*8 + g];
                mma_tf32(c[0][n], a[0][0], a[0][1], a[0][2], a[0][3], b0, b1);
                mma_tf32(c[1][n], a[1][0], a[1][1], a[1][2], a[1][3], b0, b1);
            }
        }
    }

    // Epilogue: route each n-tile to g_q / g_k / g_v
    #pragma unroll
    for (int mt = 0; mt < 2; mt++)
        #pragma unroll
        for (int n = 0; n < 6; n++) {
            int gcol = n0 + n*8 + tig*2;
            int sel  = gcol >> 6;
            int lcol = gcol & 63;
            float* dst = (sel == 0) ? g_q : (sel == 1) ? g_k : g_v;
            float b0v = g_bb[gcol], b1v = g_bb[gcol + 1];
            size_t row = r0 + m0 + mt*16 + g;
            *(float2*)&dst[row * DI + lcol] =
                make_float2(rnd_tf32(c[mt][n][0] + b0v), rnd_tf32(c[mt][n][1] + b1v));
            *(float2*)&dst[(row + 8) * DI + lcol] =
                make_float2(rnd_tf32(c[mt][n][2] + b0v), rnd_tf32(c[mt][n][3] + b1v));
        }
}

// ---------------------------------------------------------------------------
// Split-KV flash attention. q-tile 128 (8 warps x m16), kv tile 64,
// chunk = 8 kv tiles => 40 units/batch, 320 blocks x 256 threads.
// K/V double-buffered via cp.async; P A-fragments via shfl (no smem trip).
// ---------------------------------------------------------------------------
#define QST 68
#define KST 68
#define VST 72
#define OFF_K 8704
#define OFF_V 17408

__global__ __launch_bounds__(256)
void attn_part_kernel()
{
    extern __shared__ uint32_t smu[];
    uint32_t (*Qs)[QST] = (uint32_t(*)[QST])(smu);
    const uint32_t sb = (uint32_t)__cvta_generic_to_shared(smu);

    const int t    = threadIdx.x;
    const int lane = t & 31;
    const int g    = lane >> 2;
    const int tig  = lane & 3;
    const int m0   = (t >> 5) * 16;

    const int b = blockIdx.x / 40;
    int u = blockIdx.x % 40;
    int qt = 0, s = 0;
    #pragma unroll 1
    for (qt = 0; qt < 16; qt++) {
        int ns = ((2*qt + 1) >> 3) + 1;
        if (u < ns) { s = u; break; }
        u -= ns;
    }
    const int q0  = qt * 128;
    const int jt0 = s * 8;
    const int jt1 = min(jt0 + 8, 2*qt + 2);

    const float* qp = g_q + ((size_t)b * SEQ + q0) * DI;
    #pragma unroll
    for (int it = 0; it < 8; it++) {
        int idx = t + it * 256;
        int row = idx >> 4;
        int c4  = (idx & 15) << 2;
        *(uint4*)&Qs[row][c4] = *(const uint4*)&qp[row * DI + c4];
    }

    auto cp_tile = [&](int jt, int buf) {
        const float* kp = g_k + ((size_t)b * SEQ + jt * 64) * DI;
        const float* vp = g_v + ((size_t)b * SEQ + jt * 64) * DI;
        uint32_t kb = sb + (OFF_K + buf * 64*KST) * 4;
        uint32_t vb = sb + (OFF_V + buf * 64*VST) * 4;
        #pragma unroll
        for (int it = 0; it < 4; it++) {
            int idx = t + it * 256;
            int row = idx >> 4;
            int c4  = (idx & 15) << 2;
            cpa16(kb + (row * KST + c4) * 4, kp + row * DI + c4);
            cpa16(vb + (row * VST + c4) * 4, vp + row * DI + c4);
        }
        cpa_commit();
    };

    cp_tile(jt0, 0);

    float m0r = -1e30f, m1r = -1e30f, l0r = 0.f, l1r = 0.f;
    float o[8][4];
    #pragma unroll
    for (int n = 0; n < 8; n++)
        #pragma unroll
        for (int j = 0; j < 4; j++) o[n][j] = 0.f;

    for (int jt = jt0; jt < jt1; jt++) {
        const int buf = (jt - jt0) & 1;
        const uint32_t* Ks = smu + OFF_K + buf * 64*KST;
        const uint32_t* Vs = smu + OFF_V + buf * 64*VST;

        if (jt + 1 < jt1) { cp_tile(jt + 1, buf ^ 1); cpa_wait<1>(); }
        else              { cpa_wait<0>(); }
        __syncthreads();

        float sv[8][4];
        #pragma unroll
        for (int n = 0; n < 8; n++)
            #pragma unroll
            for (int j = 0; j < 4; j++) sv[n][j] = 0.f;

        #pragma unroll
        for (int kk = 0; kk < 64; kk += 8) {
            uint32_t a0 = Qs[m0+g][kk+tig];
            uint32_t a1 = Qs[m0+g+8][kk+tig];
            uint32_t a2 = Qs[m0+g][kk+tig+4];
            uint32_t a3 = Qs[m0+g+8][kk+tig+4];
            #pragma unroll
            for (int n = 0; n < 8; n++) {
                uint32_t b0 = Ks[(n*8+g) * KST + kk+tig];
                uint32_t b1 = Ks[(n*8+g) * KST + kk+tig+4];
                mma_tf32(sv[n], a0, a1, a2, a3, b0, b1);
            }
        }

        const int row0 = q0 + m0 + g;
        const int row1 = row0 + 8;
        if (jt >= 2*qt) {
            #pragma unroll
            for (int n = 0; n < 8; n++) {
                int col = jt*64 + n*8 + tig*2;
                if (col     > row0) sv[n][0] = -1e30f;
                if (col + 1 > row0) sv[n][1] = -1e30f;
                if (col     > row1) sv[n][2] = -1e30f;
                if (col + 1 > row1) sv[n][3] = -1e30f;
            }
        }

        float mx0 = -1e30f, mx1 = -1e30f;
        #pragma unroll
        for (int n = 0; n < 8; n++) {
            mx0 = fmaxf(mx0, fmaxf(sv[n][0], sv[n][1]));
            mx1 = fmaxf(mx1, fmaxf(sv[n][2], sv[n][3]));
        }
        mx0 = fmaxf(mx0, __shfl_xor_sync(0xffffffffu, mx0, 1));
        mx0 = fmaxf(mx0, __shfl_xor_sync(0xffffffffu, mx0, 2));
        mx1 = fmaxf(mx1, __shfl_xor_sync(0xffffffffu, mx1, 1));
        mx1 = fmaxf(mx1, __shfl_xor_sync(0xffffffffu, mx1, 2));

        float nm0 = fmaxf(m0r, mx0), nm1 = fmaxf(m1r, mx1);
        float sc0 = __expf(m0r - nm0), sc1 = __expf(m1r - nm1);
        float rs0 = 0.f, rs1 = 0.f;
        uint32_t pv[8][4];
        #pragma unroll
        for (int n = 0; n < 8; n++) {
            float p00 = __expf(sv[n][0] - nm0);
            float p01 = __expf(sv[n][1] - nm0);
            float p10 = __expf(sv[n][2] - nm1);
            float p11 = __expf(sv[n][3] - nm1);
            rs0 += p00 + p01;
            rs1 += p10 + p11;
            pv[n][0] = f2tf32(p00); pv[n][1] = f2tf32(p01);
            pv[n][2] = f2tf32(p10); pv[n][3] = f2tf32(p11);
            o[n][0] *= sc0; o[n][1] *= sc0;
            o[n][2] *= sc1; o[n][3] *= sc1;
        }
        rs0 += __shfl_xor_sync(0xffffffffu, rs0, 1);
        rs0 += __shfl_xor_sync(0xffffffffu, rs0, 2);
        rs1 += __shfl_xor_sync(0xffffffffu, rs1, 1);
        rs1 += __shfl_xor_sync(0xffffffffu, rs1, 2);
        l0r = l0r * sc0 + rs0; m0r = nm0;
        l1r = l1r * sc1 + rs1; m1r = nm1;

        const int Lsrc = (lane & ~3) | (tig >> 1);
        #pragma unroll
        for (int n = 0; n < 8; n++) {
            uint32_t s00 = __shfl_sync(0xffffffffu, pv[n][0], Lsrc);
            uint32_t s01 = __shfl_sync(0xffffffffu, pv[n][1], Lsrc);
            uint32_t s10 = __shfl_sync(0xffffffffu, pv[n][2], Lsrc);
            uint32_t s11 = __shfl_sync(0xffffffffu, pv[n][3], Lsrc);
            uint32_t t00 = __shfl_sync(0xffffffffu, pv[n][0], Lsrc + 2);
            uint32_t t01 = __shfl_sync(0xffffffffu, pv[n][1], Lsrc + 2);
            uint32_t t10 = __shfl_sync(0xffffffffu, pv[n][2], Lsrc + 2);
            uint32_t t11 = __shfl_sync(0xffffffffu, pv[n][3], Lsrc + 2);
            uint32_t a0 = (tig & 1) ? s01 : s00;
            uint32_t a1 = (tig & 1) ? s11 : s10;
            uint32_t a2 = (tig & 1) ? t01 : t00;
            uint32_t a3 = (tig & 1) ? t11 : t10;
            const int kk = n * 8;
            #pragma unroll
            for (int n2 = 0; n2 < 8; n2++) {
                uint32_t b0 = Vs[(kk+tig)   * VST + n2*8 + g];
                uint32_t b1 = Vs[(kk+tig+4) * VST + n2*8 + g];
                mma_tf32(o[n2], a0, a1, a2, a3, b0, b1);
            }
        }
        __syncthreads();
    }

    const int unit = ((b * 16 + qt) << 2) + s;
    float* Od = g_opart + (size_t)unit * 128 * 64;
    if (tig == 0) {
        g_mpart[unit*128 + m0 + g]     = m0r;
        g_lpart[unit*128 + m0 + g]     = l0r;
        g_mpart[unit*128 + m0 + g + 8] = m1r;
        g_lpart[unit*128 + m0 + g + 8] = l1r;
    }
    #pragma unroll
    for (int n = 0; n < 8; n++) {
        int col = n*8 + tig*2;
        *(float2*)&Od[(m0 + g) * 64 + col]     = make_float2(o[n][0], o[n][1]);
        *(float2*)&Od[(m0 + g + 8) * 64 + col] = make_float2(o[n][2], o[n][3]);
    }
}

// ---------------------------------------------------------------------------
// Combine partials + normalize + fused output projection.
// ---------------------------------------------------------------------------
#define TSTR 68

__global__ __launch_bounds__(128)
void combine_kernel(const float* __restrict__ W0, const float* __restrict__ b0,
                    float* __restrict__ out)
{
    __shared__ float scale_s[4][64];
    __shared__ float invl_s[64];
    __shared__ float Ot[64][TSTR];
    __shared__ float Ws[64][TSTR];

    const int t    = threadIdx.x;
    const int tx   = t & 15;
    const int ty   = t >> 4;
    const int b    = blockIdx.x >> 5;
    const int qh   = blockIdx.x & 31;
    const int qt   = qh >> 1;
    const int half = qh & 1;
    const int ro   = half * 64;
    const int ns   = ((2*qt + 1) >> 3) + 1;
    const int base = (b * 16 + qt) << 2;

    if (t < 64) {
        float ms[4];
        float mm = -1e30f;
        for (int s = 0; s < ns; s++) {
            ms[s] = g_mpart[(base + s) * 128 + ro + t];
            mm = fmaxf(mm, ms[s]);
        }
        float ll = 0.f;
        for (int s = 0; s < ns; s++) {
            float sc = __expf(ms[s] - mm);
            scale_s[s][t] = sc;
            ll += g_lpart[(base + s) * 128 + ro + t] * sc;
        }
        invl_s[t] = 1.0f / ll;
    }
    #pragma unroll
    for (int it = 0; it < 8; it++) {
        int idx = t + it * 128;
        int row = idx >> 4;
        int c   = (idx & 15) << 2;
        *(float4*)&Ws[row][c] = *(const float4*)&W0[row * 64 + c];
    }
    __syncthreads();

    #pragma unroll
    for (int i = 0; i < 8; i++) {
        int row = ty * 8 + i;
        float4 v = make_float4(0.f, 0.f, 0.f, 0.f);
        for (int s = 0; s < ns; s++) {
            const float* Op = g_opart + (size_t)(base + s) * 8192;
            float4 o4 = *(const float4*)&Op[(ro + row) * 64 + tx*4];
            float sc = scale_s[s][row];
            v.x = fmaf(o4.x, sc, v.x); v.y = fmaf(o4.y, sc, v.y);
            v.z = fmaf(o4.z, sc, v.z); v.w = fmaf(o4.w, sc, v.w);
        }
        float inv = invl_s[row];
        Ot[tx*4 + 0][row] = v.x * inv;
        Ot[tx*4 + 1][row] = v.y * inv;
        Ot[tx*4 + 2][row] = v.z * inv;
        Ot[tx*4 + 3][row] = v.w * inv;
    }
    __syncthreads();

    float res[8][4];
    #pragma unroll
    for (int i = 0; i < 8; i++)
        #pragma unroll
        for (int j = 0; j < 4; j++) res[i][j] = 0.f;

    #pragma unroll 8
    for (int e = 0; e < 64; e++) {
        float4 a0 = *(const float4*)&Ot[e][ty*8];
        float4 a1 = *(const float4*)&Ot[e][ty*8 + 4];
        float4 w4 = *(const float4*)&Ws[e][tx*4];
        float av[8] = {a0.x,a0.y,a0.z,a0.w,a1.x,a1.y,a1.z,a1.w};
        float wv[4] = {w4.x,w4.y,w4.z,w4.w};
        #pragma unroll
        for (int i = 0; i < 8; i++)
            #pragma unroll
            for (int o2 = 0; o2 < 4; o2++)
                res[i][o2] = fmaf(av[i], wv[o2], res[i][o2]);
    }

    float4 bb = *(const float4*)&b0[tx*4];
    float bv4[4] = {bb.x, bb.y, bb.z, bb.w};
    #pragma unroll
    for (int i = 0; i < 8; i++) {
        float4 o4;
        o4.x = res[i][0] + bv4[0];
        o4.y = res[i][1] + bv4[1];
        o4.z = res[i][2] + bv4[2];
        o4.w = res[i][3] + bv4[3];
        *(float4*)&out[((size_t)b * SEQ + qt*128 + ro + ty*8 + i) * DI + tx*4] = o4;
    }
}

// ---------------------------------------------------------------------------
extern "C" void kernel_launch(void* const* d_in, const int* in_sizes, int n_in,
                              void* d_out, int out_size)
{
    const float* X  = (const float*)d_in[0];
    const float* Wk = (const float*)d_in[1];
    const float* bk = (const float*)d_in[2];
    const float* Wq = (const float*)d_in[3];
    const float* bq = (const float*)d_in[4];
    const float* Wv = (const float*)d_in[5];
    const float* bv = (const float*)d_in[6];
    const float* W0 = (const float*)d_in[7];
    const float* b0 = (const float*)d_in[8];
    float* out = (float*)d_out;

    const int attn_smem = (128*QST + 2*64*KST + 2*64*VST) * (int)sizeof(uint32_t); // 106496
    cudaFuncSetAttribute(attn_part_kernel, cudaFuncAttributeMaxDynamicSharedMemorySize,
                         attn_smem);

    prep_kernel<<<(DM*192 + 255)/256, 256>>>(Wq, bq, Wk, bk, Wv, bv);
    proj_kernel<<<NB * SEQ / 64, 256>>>(X);
    attn_part_kernel<<<NB * 40, 256, attn_smem>>>();
    combine_kernel<<<NB * 32, 128>>>(W0, b0, out);
}

// round 14
// speedup vs baseline: 3.6473x; 1.0254x over previous
#include <cuda_runtime.h>
#include <cstdint>

#define SEQ 2048
#define DM  1024
#define DI  64
#define NB  8

__device__ float g_q[NB*SEQ*DI];   // tf32-rounded, Q pre-scaled by 1/8
__device__ float g_k[NB*SEQ*DI];
__device__ float g_v[NB*SEQ*DI];

__device__ uint32_t g_wb[DM*192];  // fused [Wq/8 | Wk | Wv] as tf32 bits, k-major
__device__ float    g_bb[192];     // fused [bq/8 | bk | bv]

// Split partials: q-tile=128 rows, up to 4 splits. unit = (b*16+qt)*4+s
__device__ float g_opart[NB*16*4*128*64];
__device__ float g_mpart[NB*16*4*128];
__device__ float g_lpart[NB*16*4*128];

__device__ __forceinline__ uint32_t f2tf32(float x) {
    uint32_t r;
    asm("cvt.rna.tf32.f32 %0, %1;" : "=r"(r) : "f"(x));
    return r;
}
__device__ __forceinline__ float rnd_tf32(float x) {
    return __uint_as_float(f2tf32(x));
}

__device__ __forceinline__ void mma_tf32(float c[4],
    uint32_t a0, uint32_t a1, uint32_t a2, uint32_t a3,
    uint32_t b0, uint32_t b1)
{
    asm volatile(
        "mma.sync.aligned.m16n8k8.row.col.f32.tf32.tf32.f32 "
        "{%0,%1,%2,%3}, {%4,%5,%6,%7}, {%8,%9}, {%0,%1,%2,%3};"
        : "+f"(c[0]), "+f"(c[1]), "+f"(c[2]), "+f"(c[3])
        : "r"(a0), "r"(a1), "r"(a2), "r"(a3), "r"(b0), "r"(b1));
}

__device__ __forceinline__ void cpa16(uint32_t dst, const void* src) {
    asm volatile("cp.async.ca.shared.global [%0], [%1], 16;" :: "r"(dst), "l"(src));
}
__device__ __forceinline__ void cpa_commit() {
    asm volatile("cp.async.commit_group;");
}
template<int N> __device__ __forceinline__ void cpa_wait() {
    asm volatile("cp.async.wait_group %0;" :: "n"(N));
}

// ---------------------------------------------------------------------------
// Prep: fuse + tf32-round the three weight matrices (Wq pre-scaled by 1/8).
// ---------------------------------------------------------------------------
__global__ void prep_kernel(const float* __restrict__ Wq, const float* __restrict__ bq,
                            const float* __restrict__ Wk, const float* __restrict__ bk,
                            const float* __restrict__ Wv, const float* __restrict__ bv)
{
    int i = blockIdx.x * 256 + threadIdx.x;
    if (i < DM * 192) {
        int k = i / 192, n = i % 192;
        const float* W = (n < 64) ? Wq : (n < 128) ? Wk : Wv;
        float v = W[k * 64 + (n & 63)];
        if (n < 64) v *= 0.125f;
        g_wb[i] = f2tf32(v);
    }
    if (i < 192) {
        const float* B = (i < 64) ? bq : (i < 128) ? bk : bv;
        float v = B[i & 63];
        if (i < 64) v *= 0.125f;
        g_bb[i] = v;
    }
}

// ---------------------------------------------------------------------------
// Fused QKV projection: C[16384 x 192] = X[16384 x 1024] * g_wb + g_bb.
// 256 blocks x 256 threads; block tile 64x192; warp m32 x n48; K-chunk 16;
// A reg-staged + cvt, B via cp.async (pre-converted); double buffered.
// ---------------------------------------------------------------------------
#define NCH 64

__global__ __launch_bounds__(256, 2)
void proj_kernel(const float* __restrict__ X)
{
    __shared__ uint32_t As[2][64][20];
    __shared__ uint32_t Bs[2][16][200];

    const int t    = threadIdx.x;
    const int w    = t >> 5;
    const int wr   = w & 1;
    const int wc   = w >> 1;
    const int lane = t & 31;
    const int g    = lane >> 2;
    const int tig  = lane & 3;
    const int m0   = wr * 32;
    const int n0   = wc * 48;
    const size_t r0 = (size_t)blockIdx.x * 64;

    const int arow = t >> 2;
    const int akc  = (t & 3) << 2;
    const float* aptr = X + (r0 + arow) * DM + akc;

    int bkr[3], bc4[3];
    #pragma unroll
    for (int it = 0; it < 3; it++) {
        int idx = t + it * 256;
        bkr[it] = idx / 48;
        bc4[it] = (idx % 48) << 2;
    }

    float4 ra;
    auto loadA = [&](int kb) { ra = *(const float4*)(aptr + kb); };
    auto storeA = [&](int p) {
        *(uint4*)&As[p][arow][akc] =
            make_uint4(f2tf32(ra.x), f2tf32(ra.y), f2tf32(ra.z), f2tf32(ra.w));
    };
    auto cpB = [&](int ci, int p) {
        #pragma unroll
        for (int it = 0; it < 3; it++) {
            uint32_t d = (uint32_t)__cvta_generic_to_shared(&Bs[p][bkr[it]][bc4[it]]);
            cpa16(d, g_wb + (size_t)(ci * 16 + bkr[it]) * 192 + bc4[it]);
        }
        cpa_commit();
    };

    float c[2][6][4];
    #pragma unroll
    for (int mt = 0; mt < 2; mt++)
        #pragma unroll
        for (int n = 0; n < 6; n++)
            #pragma unroll
            for (int j = 0; j < 4; j++) c[mt][n][j] = 0.f;

    loadA(0); storeA(0); cpB(0, 0);
    loadA(16);

    #pragma unroll 1
    for (int ci = 0; ci < NCH; ci++) {
        const int p = ci & 1;
        cpa_wait<0>();
        __syncthreads();
        if (ci + 1 < NCH) {
            storeA(p ^ 1);
            cpB(ci + 1, p ^ 1);
            if (ci + 2 < NCH) loadA((ci + 2) * 16);
        }
        #pragma unroll
        for (int kk = 0; kk < 16; kk += 8) {
            uint32_t a[2][4];
            #pragma unroll
            for (int mt = 0; mt < 2; mt++) {
                int r = m0 + mt * 16 + g;
                a[mt][0] = As[p][r][kk + tig];
                a[mt][1] = As[p][r + 8][kk + tig];
                a[mt][2] = As[p][r][kk + tig + 4];
                a[mt][3] = As[p][r + 8][kk + tig + 4];
            }
            #pragma unroll
            for (int n = 0; n < 6; n++) {
                uint32_t b0 = Bs[p][kk + tig][n0 + n*8 + g];
                uint32_t b1 = Bs[p][kk + tig + 4][n0 + n*8 + g];
                mma_tf32(c[0][n], a[0][0], a[0][1], a[0][2], a[0][3], b0, b1);
                mma_tf32(c[1][n], a[1][0], a[1][1], a[1][2], a[1][3], b0, b1);
            }
        }
    }

    #pragma unroll
    for (int mt = 0; mt < 2; mt++)
        #pragma unroll
        for (int n = 0; n < 6; n++) {
            int gcol = n0 + n*8 + tig*2;
            int sel  = gcol >> 6;
            int lcol = gcol & 63;
            float* dst = (sel == 0) ? g_q : (sel == 1) ? g_k : g_v;
            float b0v = g_bb[gcol], b1v = g_bb[gcol + 1];
            size_t row = r0 + m0 + mt*16 + g;
            *(float2*)&dst[row * DI + lcol] =
                make_float2(rnd_tf32(c[mt][n][0] + b0v), rnd_tf32(c[mt][n][1] + b1v));
            *(float2*)&dst[(row + 8) * DI + lcol] =
                make_float2(rnd_tf32(c[mt][n][2] + b0v), rnd_tf32(c[mt][n][3] + b1v));
        }
}

// ---------------------------------------------------------------------------
// Split-KV flash attention. q-tile 128 (8 warps x m16), kv tile 64,
// chunk = 8 kv tiles => 40 units/batch, 320 blocks x 256 threads.
// Units scheduled LONGEST-FIRST (u reversed) so the tail wave gets short units.
// ---------------------------------------------------------------------------
#define QST 68
#define KST 68
#define VST 72
#define OFF_K 8704
#define OFF_V 17408

__global__ __launch_bounds__(256)
void attn_part_kernel()
{
    extern __shared__ uint32_t smu[];
    uint32_t (*Qs)[QST] = (uint32_t(*)[QST])(smu);
    const uint32_t sb = (uint32_t)__cvta_generic_to_shared(smu);

    const int t    = threadIdx.x;
    const int lane = t & 31;
    const int g    = lane >> 2;
    const int tig  = lane & 3;
    const int m0   = (t >> 5) * 16;

    const int b = blockIdx.x / 40;
    int u = 39 - (blockIdx.x % 40);   // longest units (high qt) first
    int qt = 0, s = 0;
    #pragma unroll 1
    for (qt = 0; qt < 16; qt++) {
        int ns = ((2*qt + 1) >> 3) + 1;
        if (u < ns) { s = u; break; }
        u -= ns;
    }
    const int q0  = qt * 128;
    const int jt0 = s * 8;
    const int jt1 = min(jt0 + 8, 2*qt + 2);

    const float* qp = g_q + ((size_t)b * SEQ + q0) * DI;
    #pragma unroll
    for (int it = 0; it < 8; it++) {
        int idx = t + it * 256;
        int row = idx >> 4;
        int c4  = (idx & 15) << 2;
        *(uint4*)&Qs[row][c4] = *(const uint4*)&qp[row * DI + c4];
    }

    auto cp_tile = [&](int jt, int buf) {
        const float* kp = g_k + ((size_t)b * SEQ + jt * 64) * DI;
        const float* vp = g_v + ((size_t)b * SEQ + jt * 64) * DI;
        uint32_t kb = sb + (OFF_K + buf * 64*KST) * 4;
        uint32_t vb = sb + (OFF_V + buf * 64*VST) * 4;
        #pragma unroll
        for (int it = 0; it < 4; it++) {
            int idx = t + it * 256;
            int row = idx >> 4;
            int c4  = (idx & 15) << 2;
            cpa16(kb + (row * KST + c4) * 4, kp + row * DI + c4);
            cpa16(vb + (row * VST + c4) * 4, vp + row * DI + c4);
        }
        cpa_commit();
    };

    cp_tile(jt0, 0);

    float m0r = -1e30f, m1r = -1e30f, l0r = 0.f, l1r = 0.f;
    float o[8][4];
    #pragma unroll
    for (int n = 0; n < 8; n++)
        #pragma unroll
        for (int j = 0; j < 4; j++) o[n][j] = 0.f;

    for (int jt = jt0; jt < jt1; jt++) {
        const int buf = (jt - jt0) & 1;
        const uint32_t* Ks = smu + OFF_K + buf * 64*KST;
        const uint32_t* Vs = smu + OFF_V + buf * 64*VST;

        if (jt + 1 < jt1) { cp_tile(jt + 1, buf ^ 1); cpa_wait<1>(); }
        else              { cpa_wait<0>(); }
        __syncthreads();

        float sv[8][4];
        #pragma unroll
        for (int n = 0; n < 8; n++)
            #pragma unroll
            for (int j = 0; j < 4; j++) sv[n][j] = 0.f;

        #pragma unroll
        for (int kk = 0; kk < 64; kk += 8) {
            uint32_t a0 = Qs[m0+g][kk+tig];
            uint32_t a1 = Qs[m0+g+8][kk+tig];
            uint32_t a2 = Qs[m0+g][kk+tig+4];
            uint32_t a3 = Qs[m0+g+8][kk+tig+4];
            #pragma unroll
            for (int n = 0; n < 8; n++) {
                uint32_t b0 = Ks[(n*8+g) * KST + kk+tig];
                uint32_t b1 = Ks[(n*8+g) * KST + kk+tig+4];
                mma_tf32(sv[n], a0, a1, a2, a3, b0, b1);
            }
        }

        const int row0 = q0 + m0 + g;
        const int row1 = row0 + 8;
        if (jt >= 2*qt) {
            #pragma unroll
            for (int n = 0; n < 8; n++) {
                int col = jt*64 + n*8 + tig*2;
                if (col     > row0) sv[n][0] = -1e30f;
                if (col + 1 > row0) sv[n][1] = -1e30f;
                if (col     > row1) sv[n][2] = -1e30f;
                if (col + 1 > row1) sv[n][3] = -1e30f;
            }
        }

        float mx0 = -1e30f, mx1 = -1e30f;
        #pragma unroll
        for (int n = 0; n < 8; n++) {
            mx0 = fmaxf(mx0, fmaxf(sv[n][0], sv[n][1]));
            mx1 = fmaxf(mx1, fmaxf(sv[n][2], sv[n][3]));
        }
        mx0 = fmaxf(mx0, __shfl_xor_sync(0xffffffffu, mx0, 1));
        mx0 = fmaxf(mx0, __shfl_xor_sync(0xffffffffu, mx0, 2));
        mx1 = fmaxf(mx1, __shfl_xor_sync(0xffffffffu, mx1, 1));
        mx1 = fmaxf(mx1, __shfl_xor_sync(0xffffffffu, mx1, 2));

        float nm0 = fmaxf(m0r, mx0), nm1 = fmaxf(m1r, mx1);
        float sc0 = __expf(m0r - nm0), sc1 = __expf(m1r - nm1);
        float rs0 = 0.f, rs1 = 0.f;
        uint32_t pv[8][4];
        #pragma unroll
        for (int n = 0; n < 8; n++) {
            float p00 = __expf(sv[n][0] - nm0);
            float p01 = __expf(sv[n][1] - nm0);
            float p10 = __expf(sv[n][2] - nm1);
            float p11 = __expf(sv[n][3] - nm1);
            rs0 += p00 + p01;
            rs1 += p10 + p11;
            pv[n][0] = f2tf32(p00); pv[n][1] = f2tf32(p01);
            pv[n][2] = f2tf32(p10); pv[n][3] = f2tf32(p11);
            o[n][0] *= sc0; o[n][1] *= sc0;
            o[n][2] *= sc1; o[n][3] *= sc1;
        }
        rs0 += __shfl_xor_sync(0xffffffffu, rs0, 1);
        rs0 += __shfl_xor_sync(0xffffffffu, rs0, 2);
        rs1 += __shfl_xor_sync(0xffffffffu, rs1, 1);
        rs1 += __shfl_xor_sync(0xffffffffu, rs1, 2);
        l0r = l0r * sc0 + rs0; m0r = nm0;
        l1r = l1r * sc1 + rs1; m1r = nm1;

        const int Lsrc = (lane & ~3) | (tig >> 1);
        #pragma unroll
        for (int n = 0; n < 8; n++) {
            uint32_t s00 = __shfl_sync(0xffffffffu, pv[n][0], Lsrc);
            uint32_t s01 = __shfl_sync(0xffffffffu, pv[n][1], Lsrc);
            uint32_t s10 = __shfl_sync(0xffffffffu, pv[n][2], Lsrc);
            uint32_t s11 = __shfl_sync(0xffffffffu, pv[n][3], Lsrc);
            uint32_t t00 = __shfl_sync(0xffffffffu, pv[n][0], Lsrc + 2);
            uint32_t t01 = __shfl_sync(0xffffffffu, pv[n][1], Lsrc + 2);
            uint32_t t10 = __shfl_sync(0xffffffffu, pv[n][2], Lsrc + 2);
            uint32_t t11 = __shfl_sync(0xffffffffu, pv[n][3], Lsrc + 2);
            uint32_t a0 = (tig & 1) ? s01 : s00;
            uint32_t a1 = (tig & 1) ? s11 : s10;
            uint32_t a2 = (tig & 1) ? t01 : t00;
            uint32_t a3 = (tig & 1) ? t11 : t10;
            const int kk = n * 8;
            #pragma unroll
            for (int n2 = 0; n2 < 8; n2++) {
                uint32_t b0 = Vs[(kk+tig)   * VST + n2*8 + g];
                uint32_t b1 = Vs[(kk+tig+4) * VST + n2*8 + g];
                mma_tf32(o[n2], a0, a1, a2, a3, b0, b1);
            }
        }
        __syncthreads();
    }

    const int unit = ((b * 16 + qt) << 2) + s;
    float* Od = g_opart + (size_t)unit * 128 * 64;
    if (tig == 0) {
        g_mpart[unit*128 + m0 + g]     = m0r;
        g_lpart[unit*128 + m0 + g]     = l0r;
        g_mpart[unit*128 + m0 + g + 8] = m1r;
        g_lpart[unit*128 + m0 + g + 8] = l1r;
    }
    #pragma unroll
    for (int n = 0; n < 8; n++) {
        int col = n*8 + tig*2;
        *(float2*)&Od[(m0 + g) * 64 + col]     = make_float2(o[n][0], o[n][1]);
        *(float2*)&Od[(m0 + g + 8) * 64 + col] = make_float2(o[n][2], o[n][3]);
    }
}

// ---------------------------------------------------------------------------
// Combine partials + normalize + fused output projection.
// One block per (b, qt, quarter32) = 512 blocks, 128 threads, 32 rows each.
// ---------------------------------------------------------------------------
__global__ __launch_bounds__(128)
void combine_kernel(const float* __restrict__ W0, const float* __restrict__ b0,
                    float* __restrict__ out)
{
    __shared__ float scale_s[4][32];
    __shared__ float invl_s[32];
    __shared__ float Ot[64][36];    // combined O^T: [e][i], 32 rows
    __shared__ float Ws[64][68];    // W0: [e][o]

    const int t    = threadIdx.x;
    const int tx   = t & 15;
    const int ty   = t >> 4;
    const int b    = blockIdx.x >> 6;
    const int qq   = blockIdx.x & 63;
    const int qt   = qq >> 2;
    const int ro   = (qq & 3) * 32;
    const int ns   = ((2*qt + 1) >> 3) + 1;
    const int base = (b * 16 + qt) << 2;

    if (t < 32) {
        float ms[4];
        float mm = -1e30f;
        for (int s = 0; s < ns; s++) {
            ms[s] = g_mpart[(base + s) * 128 + ro + t];
            mm = fmaxf(mm, ms[s]);
        }
        float ll = 0.f;
        for (int s = 0; s < ns; s++) {
            float sc = __expf(ms[s] - mm);
            scale_s[s][t] = sc;
            ll += g_lpart[(base + s) * 128 + ro + t] * sc;
        }
        invl_s[t] = 1.0f / ll;
    }
    #pragma unroll
    for (int it = 0; it < 8; it++) {
        int idx = t + it * 128;
        int row = idx >> 4;
        int c   = (idx & 15) << 2;
        *(float4*)&Ws[row][c] = *(const float4*)&W0[row * 64 + c];
    }
    __syncthreads();

    // Combine partials for 32 rows; each thread: 2 rows x 4 cols
    #pragma unroll
    for (int i = 0; i < 2; i++) {
        int row = ty * 2 + i + ((tx >> 3) << 4);   // spread rows across tx halves
        // simpler exact mapping: thread handles rows ty*2+i with 16 col-threads
        row = ty * 2 + i;                           // rows 0..15 for ty 0..7
        // two passes: rows 0-15 and 16-31
        #pragma unroll
        for (int h = 0; h < 2; h++) {
            int r2 = row + h * 16;
            float4 v = make_float4(0.f, 0.f, 0.f, 0.f);
            for (int s = 0; s < ns; s++) {
                const float* Op = g_opart + (size_t)(base + s) * 8192;
                float4 o4 = *(const float4*)&Op[(ro + r2) * 64 + tx*4];
                float sc = scale_s[s][r2];
                v.x = fmaf(o4.x, sc, v.x); v.y = fmaf(o4.y, sc, v.y);
                v.z = fmaf(o4.z, sc, v.z); v.w = fmaf(o4.w, sc, v.w);
            }
            float inv = invl_s[r2];
            Ot[tx*4 + 0][r2] = v.x * inv;
            Ot[tx*4 + 1][r2] = v.y * inv;
            Ot[tx*4 + 2][r2] = v.z * inv;
            Ot[tx*4 + 3][r2] = v.w * inv;
        }
    }
    __syncthreads();

    // out = O * W0 + b0 : each thread 4 rows x 4 cols
    float res[4][4];
    #pragma unroll
    for (int i = 0; i < 4; i++)
        #pragma unroll
        for (int j = 0; j < 4; j++) res[i][j] = 0.f;

    #pragma unroll 8
    for (int e = 0; e < 64; e++) {
        float4 a0 = *(const float4*)&Ot[e][ty*4];
        float4 w4 = *(const float4*)&Ws[e][tx*4];
        float av[4] = {a0.x, a0.y, a0.z, a0.w};
        float wv[4] = {w4.x, w4.y, w4.z, w4.w};
        #pragma unroll
        for (int i = 0; i < 4; i++)
            #pragma unroll
            for (int o2 = 0; o2 < 4; o2++)
                res[i][o2] = fmaf(av[i], wv[o2], res[i][o2]);
    }

    float4 bb = *(const float4*)&b0[tx*4];
    float bv4[4] = {bb.x, bb.y, bb.z, bb.w};
    #pragma unroll
    for (int i = 0; i < 4; i++) {
        float4 o4;
        o4.x = res[i][0] + bv4[0];
        o4.y = res[i][1] + bv4[1];
        o4.z = res[i][2] + bv4[2];
        o4.w = res[i][3] + bv4[3];
        *(float4*)&out[((size_t)b * SEQ + qt*128 + ro + ty*4 + i) * DI + tx*4] = o4;
    }
}

// ---------------------------------------------------------------------------
extern "C" void kernel_launch(void* const* d_in, const int* in_sizes, int n_in,
                              void* d_out, int out_size)
{
    const float* X  = (const float*)d_in[0];
    const float* Wk = (const float*)d_in[1];
    const float* bk = (const float*)d_in[2];
    const float* Wq = (const float*)d_in[3];
    const float* bq = (const float*)d_in[4];
    const float* Wv = (const float*)d_in[5];
    const float* bv = (const float*)d_in[6];
    const float* W0 = (const float*)d_in[7];
    const float* b0 = (const float*)d_in[8];
    float* out = (float*)d_out;

    const int attn_smem = (128*QST + 2*64*KST + 2*64*VST) * (int)sizeof(uint32_t); // 106496
    cudaFuncSetAttribute(attn_part_kernel, cudaFuncAttributeMaxDynamicSharedMemorySize,
                         attn_smem);

    prep_kernel<<<(DM*192 + 255)/256, 256>>>(Wq, bq, Wk, bk, Wv, bv);
    proj_kernel<<<NB * SEQ / 64, 256>>>(X);
    attn_part_kernel<<<NB * 40, 256, attn_smem>>>();
    combine_kernel<<<NB * 64, 128>>>(W0, b0, out);
}

// round 15
// speedup vs baseline: 3.6676x; 1.0056x over previous
#include <cuda_runtime.h>
#include <cuda_fp16.h>
#include <cstdint>

#define SEQ 2048
#define DM  1024
#define DI  64
#define NB  8

__device__ float g_q[NB*SEQ*DI];   // tf32-rounded, Q pre-scaled by 1/8
__device__ float g_k[NB*SEQ*DI];
__device__ float g_v[NB*SEQ*DI];

__device__ uint32_t g_wb[DM*192];  // fused [Wq/8 | Wk | Wv] tf32 bits, k-major
__device__ float    g_bb[192];     // fused [bq/8 | bk | bv]
__device__ uint32_t g_w0b[64*64];  // W0 [e][o] as tf32 bits

// Split partials (already projected through W0, fp16): unit = (b*16+qt)*4+s
__device__ __half g_opart[NB*16*4*128*64];
__device__ float  g_mpart[NB*16*4*128];
__device__ float  g_lpart[NB*16*4*128];

__device__ __forceinline__ uint32_t f2tf32(float x) {
    uint32_t r;
    asm("cvt.rna.tf32.f32 %0, %1;" : "=r"(r) : "f"(x));
    return r;
}
__device__ __forceinline__ float rnd_tf32(float x) {
    return __uint_as_float(f2tf32(x));
}

__device__ __forceinline__ void mma_tf32(float c[4],
    uint32_t a0, uint32_t a1, uint32_t a2, uint32_t a3,
    uint32_t b0, uint32_t b1)
{
    asm volatile(
        "mma.sync.aligned.m16n8k8.row.col.f32.tf32.tf32.f32 "
        "{%0,%1,%2,%3}, {%4,%5,%6,%7}, {%8,%9}, {%0,%1,%2,%3};"
        : "+f"(c[0]), "+f"(c[1]), "+f"(c[2]), "+f"(c[3])
        : "r"(a0), "r"(a1), "r"(a2), "r"(a3), "r"(b0), "r"(b1));
}

__device__ __forceinline__ void cpa16(uint32_t dst, const void* src) {
    asm volatile("cp.async.ca.shared.global [%0], [%1], 16;" :: "r"(dst), "l"(src));
}
__device__ __forceinline__ void cpa_commit() {
    asm volatile("cp.async.commit_group;");
}
template<int N> __device__ __forceinline__ void cpa_wait() {
    asm volatile("cp.async.wait_group %0;" :: "n"(N));
}

// ---------------------------------------------------------------------------
// Prep: tf32-round fused QKV weights (Wq,bq pre-scaled by 1/8) and W0.
// ---------------------------------------------------------------------------
__global__ void prep_kernel(const float* __restrict__ Wq, const float* __restrict__ bq,
                            const float* __restrict__ Wk, const float* __restrict__ bk,
                            const float* __restrict__ Wv, const float* __restrict__ bv,
                            const float* __restrict__ W0)
{
    int i = blockIdx.x * 256 + threadIdx.x;
    if (i < DM * 192) {
        int k = i / 192, n = i % 192;
        const float* W = (n < 64) ? Wq : (n < 128) ? Wk : Wv;
        float v = W[k * 64 + (n & 63)];
        if (n < 64) v *= 0.125f;
        g_wb[i] = f2tf32(v);
    }
    if (i < 192) {
        const float* B = (i < 64) ? bq : (i < 128) ? bk : bv;
        float v = B[i & 63];
        if (i < 64) v *= 0.125f;
        g_bb[i] = v;
    }
    if (i < 64 * 64) g_w0b[i] = f2tf32(W0[i]);
}

// ---------------------------------------------------------------------------
// Fused QKV projection: C[16384 x 192] = X[16384 x 1024] * g_wb + g_bb.
// ---------------------------------------------------------------------------
#define NCH 64

__global__ __launch_bounds__(256, 2)
void proj_kernel(const float* __restrict__ X)
{
    __shared__ uint32_t As[2][64][20];
    __shared__ uint32_t Bs[2][16][200];

    const int t    = threadIdx.x;
    const int w    = t >> 5;
    const int wr   = w & 1;
    const int wc   = w >> 1;
    const int lane = t & 31;
    const int g    = lane >> 2;
    const int tig  = lane & 3;
    const int m0   = wr * 32;
    const int n0   = wc * 48;
    const size_t r0 = (size_t)blockIdx.x * 64;

    const int arow = t >> 2;
    const int akc  = (t & 3) << 2;
    const float* aptr = X + (r0 + arow) * DM + akc;

    int bkr[3], bc4[3];
    #pragma unroll
    for (int it = 0; it < 3; it++) {
        int idx = t + it * 256;
        bkr[it] = idx / 48;
        bc4[it] = (idx % 48) << 2;
    }

    float4 ra;
    auto loadA = [&](int kb) { ra = *(const float4*)(aptr + kb); };
    auto storeA = [&](int p) {
        *(uint4*)&As[p][arow][akc] =
            make_uint4(f2tf32(ra.x), f2tf32(ra.y), f2tf32(ra.z), f2tf32(ra.w));
    };
    auto cpB = [&](int ci, int p) {
        #pragma unroll
        for (int it = 0; it < 3; it++) {
            uint32_t d = (uint32_t)__cvta_generic_to_shared(&Bs[p][bkr[it]][bc4[it]]);
            cpa16(d, g_wb + (size_t)(ci * 16 + bkr[it]) * 192 + bc4[it]);
        }
        cpa_commit();
    };

    float c[2][6][4];
    #pragma unroll
    for (int mt = 0; mt < 2; mt++)
        #pragma unroll
        for (int n = 0; n < 6; n++)
            #pragma unroll
            for (int j = 0; j < 4; j++) c[mt][n][j] = 0.f;

    loadA(0); storeA(0); cpB(0, 0);
    loadA(16);

    #pragma unroll 1
    for (int ci = 0; ci < NCH; ci++) {
        const int p = ci & 1;
        cpa_wait<0>();
        __syncthreads();
        if (ci + 1 < NCH) {
            storeA(p ^ 1);
            cpB(ci + 1, p ^ 1);
            if (ci + 2 < NCH) loadA((ci + 2) * 16);
        }
        #pragma unroll
        for (int kk = 0; kk < 16; kk += 8) {
            uint32_t a[2][4];
            #pragma unroll
            for (int mt = 0; mt < 2; mt++) {
                int r = m0 + mt * 16 + g;
                a[mt][0] = As[p][r][kk + tig];
                a[mt][1] = As[p][r + 8][kk + tig];
                a[mt][2] = As[p][r][kk + tig + 4];
                a[mt][3] = As[p][r + 8][kk + tig + 4];
            }
            #pragma unroll
            for (int n = 0; n < 6; n++) {
                uint32_t b0 = Bs[p][kk + tig][n0 + n*8 + g];
                uint32_t b1 = Bs[p][kk + tig + 4][n0 + n*8 + g];
                mma_tf32(c[0][n], a[0][0], a[0][1], a[0][2], a[0][3], b0, b1);
                mma_tf32(c[1][n], a[1][0], a[1][1], a[1][2], a[1][3], b0, b1);
            }
        }
    }

    #pragma unroll
    for (int mt = 0; mt < 2; mt++)
        #pragma unroll
        for (int n = 0; n < 6; n++) {
            int gcol = n0 + n*8 + tig*2;
            int sel  = gcol >> 6;
            int lcol = gcol & 63;
            float* dst = (sel == 0) ? g_q : (sel == 1) ? g_k : g_v;
            float b0v = g_bb[gcol], b1v = g_bb[gcol + 1];
            size_t row = r0 + m0 + mt*16 + g;
            *(float2*)&dst[row * DI + lcol] =
                make_float2(rnd_tf32(c[mt][n][0] + b0v), rnd_tf32(c[mt][n][1] + b1v));
            *(float2*)&dst[(row + 8) * DI + lcol] =
                make_float2(rnd_tf32(c[mt][n][2] + b0v), rnd_tf32(c[mt][n][3] + b1v));
        }
}

// ---------------------------------------------------------------------------
// Split-KV flash attention. q-tile 128 (8 warps x m16), kv tile 64,
// chunk = 8 kv tiles => 40 units/batch, 320 blocks x 256 threads.
// Longest-first scheduling. Epilogue projects O through W0 (tf32 mma) and
// emits fp16 partials.
// ---------------------------------------------------------------------------
#define QST 68
#define KST 68
#define VST 72
#define OFF_K 8704
#define OFF_V 17408

__global__ __launch_bounds__(256)
void attn_part_kernel()
{
    extern __shared__ uint32_t smu[];
    uint32_t (*Qs)[QST] = (uint32_t(*)[QST])(smu);
    const uint32_t sb = (uint32_t)__cvta_generic_to_shared(smu);

    const int t    = threadIdx.x;
    const int lane = t & 31;
    const int g    = lane >> 2;
    const int tig  = lane & 3;
    const int m0   = (t >> 5) * 16;

    const int b = blockIdx.x / 40;
    int u = 39 - (blockIdx.x % 40);   // longest units (high qt) first
    int qt = 0, s = 0;
    #pragma unroll 1
    for (qt = 0; qt < 16; qt++) {
        int ns = ((2*qt + 1) >> 3) + 1;
        if (u < ns) { s = u; break; }
        u -= ns;
    }
    const int q0  = qt * 128;
    const int jt0 = s * 8;
    const int jt1 = min(jt0 + 8, 2*qt + 2);

    const float* qp = g_q + ((size_t)b * SEQ + q0) * DI;
    #pragma unroll
    for (int it = 0; it < 8; it++) {
        int idx = t + it * 256;
        int row = idx >> 4;
        int c4  = (idx & 15) << 2;
        *(uint4*)&Qs[row][c4] = *(const uint4*)&qp[row * DI + c4];
    }

    auto cp_tile = [&](int jt, int buf) {
        const float* kp = g_k + ((size_t)b * SEQ + jt * 64) * DI;
        const float* vp = g_v + ((size_t)b * SEQ + jt * 64) * DI;
        uint32_t kb = sb + (OFF_K + buf * 64*KST) * 4;
        uint32_t vb = sb + (OFF_V + buf * 64*VST) * 4;
        #pragma unroll
        for (int it = 0; it < 4; it++) {
            int idx = t + it * 256;
            int row = idx >> 4;
            int c4  = (idx & 15) << 2;
            cpa16(kb + (row * KST + c4) * 4, kp + row * DI + c4);
            cpa16(vb + (row * VST + c4) * 4, vp + row * DI + c4);
        }
        cpa_commit();
    };

    cp_tile(jt0, 0);

    float m0r = -1e30f, m1r = -1e30f, l0r = 0.f, l1r = 0.f;
    float o[8][4];
    #pragma unroll
    for (int n = 0; n < 8; n++)
        #pragma unroll
        for (int j = 0; j < 4; j++) o[n][j] = 0.f;

    const int Lsrc = (lane & ~3) | (tig >> 1);

    for (int jt = jt0; jt < jt1; jt++) {
        const int buf = (jt - jt0) & 1;
        const uint32_t* Ks = smu + OFF_K + buf * 64*KST;
        const uint32_t* Vs = smu + OFF_V + buf * 64*VST;

        if (jt + 1 < jt1) { cp_tile(jt + 1, buf ^ 1); cpa_wait<1>(); }
        else              { cpa_wait<0>(); }
        __syncthreads();

        float sv[8][4];
        #pragma unroll
        for (int n = 0; n < 8; n++)
            #pragma unroll
            for (int j = 0; j < 4; j++) sv[n][j] = 0.f;

        #pragma unroll
        for (int kk = 0; kk < 64; kk += 8) {
            uint32_t a0 = Qs[m0+g][kk+tig];
            uint32_t a1 = Qs[m0+g+8][kk+tig];
            uint32_t a2 = Qs[m0+g][kk+tig+4];
            uint32_t a3 = Qs[m0+g+8][kk+tig+4];
            #pragma unroll
            for (int n = 0; n < 8; n++) {
                uint32_t b0 = Ks[(n*8+g) * KST + kk+tig];
                uint32_t b1 = Ks[(n*8+g) * KST + kk+tig+4];
                mma_tf32(sv[n], a0, a1, a2, a3, b0, b1);
            }
        }

        const int row0 = q0 + m0 + g;
        const int row1 = row0 + 8;
        if (jt >= 2*qt) {
            #pragma unroll
            for (int n = 0; n < 8; n++) {
                int col = jt*64 + n*8 + tig*2;
                if (col     > row0) sv[n][0] = -1e30f;
                if (col + 1 > row0) sv[n][1] = -1e30f;
                if (col     > row1) sv[n][2] = -1e30f;
                if (col + 1 > row1) sv[n][3] = -1e30f;
            }
        }

        float mx0 = -1e30f, mx1 = -1e30f;
        #pragma unroll
        for (int n = 0; n < 8; n++) {
            mx0 = fmaxf(mx0, fmaxf(sv[n][0], sv[n][1]));
            mx1 = fmaxf(mx1, fmaxf(sv[n][2], sv[n][3]));
        }
        mx0 = fmaxf(mx0, __shfl_xor_sync(0xffffffffu, mx0, 1));
        mx0 = fmaxf(mx0, __shfl_xor_sync(0xffffffffu, mx0, 2));
        mx1 = fmaxf(mx1, __shfl_xor_sync(0xffffffffu, mx1, 1));
        mx1 = fmaxf(mx1, __shfl_xor_sync(0xffffffffu, mx1, 2));

        float nm0 = fmaxf(m0r, mx0), nm1 = fmaxf(m1r, mx1);
        float sc0 = __expf(m0r - nm0), sc1 = __expf(m1r - nm1);
        float rs0 = 0.f, rs1 = 0.f;
        uint32_t pv[8][4];
        #pragma unroll
        for (int n = 0; n < 8; n++) {
            float p00 = __expf(sv[n][0] - nm0);
            float p01 = __expf(sv[n][1] - nm0);
            float p10 = __expf(sv[n][2] - nm1);
            float p11 = __expf(sv[n][3] - nm1);
            rs0 += p00 + p01;
            rs1 += p10 + p11;
            pv[n][0] = f2tf32(p00); pv[n][1] = f2tf32(p01);
            pv[n][2] = f2tf32(p10); pv[n][3] = f2tf32(p11);
            o[n][0] *= sc0; o[n][1] *= sc0;
            o[n][2] *= sc1; o[n][3] *= sc1;
        }
        rs0 += __shfl_xor_sync(0xffffffffu, rs0, 1);
        rs0 += __shfl_xor_sync(0xffffffffu, rs0, 2);
        rs1 += __shfl_xor_sync(0xffffffffu, rs1, 1);
        rs1 += __shfl_xor_sync(0xffffffffu, rs1, 2);
        l0r = l0r * sc0 + rs0; m0r = nm0;
        l1r = l1r * sc1 + rs1; m1r = nm1;

        #pragma unroll
        for (int n = 0; n < 8; n++) {
            uint32_t s00 = __shfl_sync(0xffffffffu, pv[n][0], Lsrc);
            uint32_t s01 = __shfl_sync(0xffffffffu, pv[n][1], Lsrc);
            uint32_t s10 = __shfl_sync(0xffffffffu, pv[n][2], Lsrc);
            uint32_t s11 = __shfl_sync(0xffffffffu, pv[n][3], Lsrc);
            uint32_t t00 = __shfl_sync(0xffffffffu, pv[n][0], Lsrc + 2);
            uint32_t t01 = __shfl_sync(0xffffffffu, pv[n][1], Lsrc + 2);
            uint32_t t10 = __shfl_sync(0xffffffffu, pv[n][2], Lsrc + 2);
            uint32_t t11 = __shfl_sync(0xffffffffu, pv[n][3], Lsrc + 2);
            uint32_t a0 = (tig & 1) ? s01 : s00;
            uint32_t a1 = (tig & 1) ? s11 : s10;
            uint32_t a2 = (tig & 1) ? t01 : t00;
            uint32_t a3 = (tig & 1) ? t11 : t10;
            const int kk = n * 8;
            #pragma unroll
            for (int n2 = 0; n2 < 8; n2++) {
                uint32_t b0 = Vs[(kk+tig)   * VST + n2*8 + g];
                uint32_t b1 = Vs[(kk+tig+4) * VST + n2*8 + g];
                mma_tf32(o[n2], a0, a1, a2, a3, b0, b1);
            }
        }
        __syncthreads();
    }

    // ---- Epilogue: project O through W0 (tf32 mma), emit fp16 partials ----
    // Load W0 [e][o] (tf32 bits) into the (now free) K-buffer region, stride 72.
    {
        #pragma unroll
        for (int it = 0; it < 4; it++) {
            int idx = t + it * 256;      // 1024 cp16 = 64x64 u32
            int e  = idx >> 4;
            int o4 = (idx & 15) << 2;
            cpa16(sb + (OFF_K + e * 72 + o4) * 4, g_w0b + e * 64 + o4);
        }
        cpa_commit();
        cpa_wait<0>();
        __syncthreads();
    }
    const uint32_t* Wp = smu + OFF_K;

    // Convert O c-fragment to tf32 A-fragments (same layout as P) and mma.
    uint32_t ov[8][4];
    #pragma unroll
    for (int n = 0; n < 8; n++) {
        ov[n][0] = f2tf32(o[n][0]); ov[n][1] = f2tf32(o[n][1]);
        ov[n][2] = f2tf32(o[n][2]); ov[n][3] = f2tf32(o[n][3]);
    }
    float res[8][4];
    #pragma unroll
    for (int n = 0; n < 8; n++)
        #pragma unroll
        for (int j = 0; j < 4; j++) res[n][j] = 0.f;

    #pragma unroll
    for (int n = 0; n < 8; n++) {          // k-group over e: kk = n*8
        uint32_t s00 = __shfl_sync(0xffffffffu, ov[n][0], Lsrc);
        uint32_t s01 = __shfl_sync(0xffffffffu, ov[n][1], Lsrc);
        uint32_t s10 = __shfl_sync(0xffffffffu, ov[n][2], Lsrc);
        uint32_t s11 = __shfl_sync(0xffffffffu, ov[n][3], Lsrc);
        uint32_t t00 = __shfl_sync(0xffffffffu, ov[n][0], Lsrc + 2);
        uint32_t t01 = __shfl_sync(0xffffffffu, ov[n][1], Lsrc + 2);
        uint32_t t10 = __shfl_sync(0xffffffffu, ov[n][2], Lsrc + 2);
        uint32_t t11 = __shfl_sync(0xffffffffu, ov[n][3], Lsrc + 2);
        uint32_t a0 = (tig & 1) ? s01 : s00;
        uint32_t a1 = (tig & 1) ? s11 : s10;
        uint32_t a2 = (tig & 1) ? t01 : t00;
        uint32_t a3 = (tig & 1) ? t11 : t10;
        const int kk = n * 8;
        #pragma unroll
        for (int n2 = 0; n2 < 8; n2++) {
            uint32_t b0 = Wp[(kk+tig)   * 72 + n2*8 + g];
            uint32_t b1 = Wp[(kk+tig+4) * 72 + n2*8 + g];
            mma_tf32(res[n2], a0, a1, a2, a3, b0, b1);
        }
    }

    const int unit = ((b * 16 + qt) << 2) + s;
    __half* Od = g_opart + (size_t)unit * 128 * 64;
    if (tig == 0) {
        g_mpart[unit*128 + m0 + g]     = m0r;
        g_lpart[unit*128 + m0 + g]     = l0r;
        g_mpart[unit*128 + m0 + g + 8] = m1r;
        g_lpart[unit*128 + m0 + g + 8] = l1r;
    }
    #pragma unroll
    for (int n2 = 0; n2 < 8; n2++) {
        int col = n2*8 + tig*2;
        *(__half2*)&Od[(m0 + g) * 64 + col]     = __floats2half2_rn(res[n2][0], res[n2][1]);
        *(__half2*)&Od[(m0 + g + 8) * 64 + col] = __floats2half2_rn(res[n2][2], res[n2][3]);
    }
}

// ---------------------------------------------------------------------------
// Combine: pure streaming merge of projected fp16 partials + bias.
// 2048 blocks x 128 threads; block = (b, qt, 8-row sub-tile); thread = 1 row
// x 4 cols. No smem, no syncthreads.
// ---------------------------------------------------------------------------
__global__ __launch_bounds__(128)
void combine_kernel(const float* __restrict__ b0, float* __restrict__ out)
{
    const int t    = threadIdx.x;
    const int blk  = blockIdx.x;
    const int b    = blk >> 8;          // /256
    const int rem  = blk & 255;
    const int qt   = rem >> 4;
    const int sub  = rem & 15;
    const int r    = sub * 8 + (t >> 4);     // row in [0,128)
    const int c    = (t & 15) * 4;
    const int ns   = ((2*qt + 1) >> 3) + 1;
    const int base = (b * 16 + qt) << 2;

    float ms[4];
    float mm = -1e30f;
    #pragma unroll 4
    for (int s = 0; s < ns; s++) {
        ms[s] = g_mpart[(base + s) * 128 + r];
        mm = fmaxf(mm, ms[s]);
    }
    float ll = 0.f;
    float sc[4];
    #pragma unroll 4
    for (int s = 0; s < ns; s++) {
        sc[s] = __expf(ms[s] - mm);
        ll += g_lpart[(base + s) * 128 + r] * sc[s];
    }
    const float inv = 1.0f / ll;

    float4 acc = make_float4(0.f, 0.f, 0.f, 0.f);
    #pragma unroll 4
    for (int s = 0; s < ns; s++) {
        const __half2* hp = (const __half2*)(g_opart + (size_t)(base + s) * 8192 + r * 64 + c);
        float2 f01 = __half22float2(hp[0]);
        float2 f23 = __half22float2(hp[1]);
        acc.x = fmaf(f01.x, sc[s], acc.x);
        acc.y = fmaf(f01.y, sc[s], acc.y);
        acc.z = fmaf(f23.x, sc[s], acc.z);
        acc.w = fmaf(f23.y, sc[s], acc.w);
    }

    float4 bb = *(const float4*)&b0[c];
    float4 o4;
    o4.x = acc.x * inv + bb.x;
    o4.y = acc.y * inv + bb.y;
    o4.z = acc.z * inv + bb.z;
    o4.w = acc.w * inv + bb.w;
    *(float4*)&out[((size_t)b * SEQ + qt * 128 + r) * DI + c] = o4;
}

// ---------------------------------------------------------------------------
extern "C" void kernel_launch(void* const* d_in, const int* in_sizes, int n_in,
                              void* d_out, int out_size)
{
    const float* X  = (const float*)d_in[0];
    const float* Wk = (const float*)d_in[1];
    const float* bk = (const float*)d_in[2];
    const float* Wq = (const float*)d_in[3];
    const float* bq = (const float*)d_in[4];
    const float* Wv = (const float*)d_in[5];
    const float* bv = (const float*)d_in[6];
    const float* W0 = (const float*)d_in[7];
    const float* b0 = (const float*)d_in[8];
    float* out = (float*)d_out;

    const int attn_smem = (128*QST + 2*64*KST + 2*64*VST) * (int)sizeof(uint32_t); // 106496
    cudaFuncSetAttribute(attn_part_kernel, cudaFuncAttributeMaxDynamicSharedMemorySize,
                         attn_smem);

    prep_kernel<<<(DM*192 + 255)/256, 256>>>(Wq, bq, Wk, bk, Wv, bv, W0);
    proj_kernel<<<NB * SEQ / 64, 256>>>(X);
    attn_part_kernel<<<NB * 40, 256, attn_smem>>>();
    combine_kernel<<<NB * 256, 128>>>(b0, out);
}